// round 1
// baseline (speedup 1.0000x reference)
#include <cuda_runtime.h>
#include <math.h>

// ---------------- problem constants ----------------
constexpr int CB = 2, CS = 1024, CD = 1024;
constexpr int CH = 16, CKV = 4, CHD = 64;
constexpr int CE = 8, CTOPK = 2, CF = 2048;
constexpr int CT = CB * CS;              // 2048 tokens
constexpr float CEPS = 1e-6f;

// ---------------- scratch (static device memory; no allocs) ----------------
__device__ float g_xn [CT * CD];                 // rmsnorm1 out
__device__ float g_q  [CT * CH  * CHD];
__device__ float g_k  [CT * CKV * CHD];
__device__ float g_v  [CT * CKV * CHD];
__device__ float g_att[CT * CH  * CHD];
__device__ float g_h1 [CT * CD];                 // residual after attention
__device__ float g_hn [CT * CD];                 // rmsnorm2 out
__device__ int   g_cnt [CE];
__device__ int   g_tok [CE * CT];
__device__ float g_wsl [CE * CT];
__device__ int   g_slot[CT * CTOPK];
__device__ float g_hexp[(size_t)CE * CT * CF];   // 134 MB: weighted SwiGLU activations
__device__ float g_y   [(size_t)CE * CT * CD];   // 67 MB: per-slot expert outputs

// ---------------- RMSNorm ----------------
__global__ void rmsnorm_kernel(const float* __restrict__ x, const float* __restrict__ w,
                               float* __restrict__ out) {
    int t = blockIdx.x;
    const float* xr = x + (size_t)t * CD;
    float ss = 0.f;
    for (int d = threadIdx.x; d < CD; d += 256) { float v = xr[d]; ss += v * v; }
    __shared__ float red[256];
    red[threadIdx.x] = ss;
    __syncthreads();
    for (int s = 128; s > 0; s >>= 1) {
        if (threadIdx.x < s) red[threadIdx.x] += red[threadIdx.x + s];
        __syncthreads();
    }
    __shared__ float rinv;
    if (threadIdx.x == 0) rinv = rsqrtf(red[0] * (1.f / CD) + CEPS);
    __syncthreads();
    float* orow = out + (size_t)t * CD;
    for (int d = threadIdx.x; d < CD; d += 256) orow[d] = xr[d] * rinv * w[d];
}

// ---------------- generic tiled GEMM: C[M,N] = A[M,K] @ B[K,N] (+ Res) ----------------
// BM=BN=64, BK=16, 256 threads, 4x4 micro-tile. M,N,K multiples of 64/16 here.
__global__ void gemm_kernel(const float* __restrict__ A, const float* __restrict__ Bw,
                            const float* __restrict__ Res, float* __restrict__ C,
                            int M, int N, int K) {
    __shared__ float As[16 * 65];   // As[kk][row]
    __shared__ float Bs[16 * 65];   // Bs[kk][col]
    int m0 = blockIdx.y * 64, n0 = blockIdx.x * 64;
    int tid = threadIdx.x, ty = tid >> 4, tx = tid & 15;
    float acc[4][4] = {};
    for (int k0 = 0; k0 < K; k0 += 16) {
        #pragma unroll
        for (int it = 0; it < 4; ++it) {
            int r  = (tid >> 4) + it * 16;
            int kk = tid & 15;
            As[kk * 65 + r] = A[(size_t)(m0 + r) * K + k0 + kk];
        }
        #pragma unroll
        for (int it = 0; it < 4; ++it) {
            int kk = (tid >> 6) + it * 4;
            int c  = tid & 63;
            Bs[kk * 65 + c] = Bw[(size_t)(k0 + kk) * N + n0 + c];
        }
        __syncthreads();
        #pragma unroll
        for (int kk = 0; kk < 16; ++kk) {
            float a[4], bb[4];
            #pragma unroll
            for (int i = 0; i < 4; ++i) a[i]  = As[kk * 65 + ty * 4 + i];
            #pragma unroll
            for (int j = 0; j < 4; ++j) bb[j] = Bs[kk * 65 + tx * 4 + j];
            #pragma unroll
            for (int i = 0; i < 4; ++i)
                #pragma unroll
                for (int j = 0; j < 4; ++j) acc[i][j] += a[i] * bb[j];
        }
        __syncthreads();
    }
    #pragma unroll
    for (int i = 0; i < 4; ++i)
        #pragma unroll
        for (int j = 0; j < 4; ++j) {
            size_t idx = (size_t)(m0 + ty * 4 + i) * N + n0 + tx * 4 + j;
            float r = Res ? Res[idx] : 0.f;
            C[idx] = acc[i][j] + r;
        }
}

// ---------------- RoPE (q and k, in place) ----------------
__global__ void rope_kernel(const int* __restrict__ pos_ids) {
    int idx = blockIdx.x * 256 + threadIdx.x;
    const int nq = CT * CH * 32;
    const int nk = CT * CKV * 32;
    if (idx >= nq + nk) return;
    float* base;
    int i, t;
    if (idx < nq) {
        i = idx & 31; int th = idx >> 5; int h = th % CH; t = th / CH;
        base = g_q + ((size_t)t * CH + h) * CHD;
    } else {
        int id2 = idx - nq;
        i = id2 & 31; int th = id2 >> 5; int h = th % CKV; t = th / CKV;
        base = g_k + ((size_t)t * CKV + h) * CHD;
    }
    float p = (float)pos_ids[t];
    float freq = expf(-(2.f * i / (float)CHD) * logf(10000.f));
    float ang = p * freq;
    float c = cosf(ang), s = sinf(ang);
    float x0 = base[i], x1 = base[i + 32];
    base[i]      = x0 * c - x1 * s;
    base[i + 32] = x1 * c + x0 * s;
}

// ---------------- flash-style causal attention ----------------
// grid: (B*H, S/64); block 256 threads; dynamic smem: 5 tiles 64x65 + m,l
constexpr int FLASH_SMEM = (5 * 64 * 65 + 128) * 4;
__global__ void flash_kernel() {
    extern __shared__ float sm[];
    float* Qs = sm;
    float* Ks = Qs + 64 * 65;
    float* Vs = Ks + 64 * 65;
    float* Ss = Vs + 64 * 65;
    float* Os = Ss + 64 * 65;
    float* mrow = Os + 64 * 65;
    float* lrow = mrow + 64;

    int bh = blockIdx.x, qt = blockIdx.y;
    int b = bh / CH, h = bh % CH, kvh = h / (CH / CKV);
    int tid = threadIdx.x, ty = tid >> 4, tx = tid & 15;

    for (int i = tid; i < 64 * 64; i += 256) {
        int r = i >> 6, d = i & 63;
        Qs[r * 65 + d] = g_q[((size_t)(b * CS + qt * 64 + r) * CH + h) * CHD + d] * 0.125f;
        Os[r * 65 + d] = 0.f;
    }
    if (tid < 64) { mrow[tid] = -INFINITY; lrow[tid] = 0.f; }
    __syncthreads();

    for (int kt = 0; kt <= qt; ++kt) {
        for (int i = tid; i < 64 * 64; i += 256) {
            int r = i >> 6, d = i & 63;
            size_t jb = (size_t)(b * CS + kt * 64 + r) * CKV + kvh;
            Ks[r * 65 + d] = g_k[jb * CHD + d];
            Vs[r * 65 + d] = g_v[jb * CHD + d];
        }
        __syncthreads();

        // S = Q K^T
        float acc[4][4] = {};
        #pragma unroll 8
        for (int kk = 0; kk < 64; ++kk) {
            float qa[4], kb[4];
            #pragma unroll
            for (int i = 0; i < 4; ++i) qa[i] = Qs[(ty * 4 + i) * 65 + kk];
            #pragma unroll
            for (int j = 0; j < 4; ++j) kb[j] = Ks[(tx * 4 + j) * 65 + kk];
            #pragma unroll
            for (int i = 0; i < 4; ++i)
                #pragma unroll
                for (int j = 0; j < 4; ++j) acc[i][j] += qa[i] * kb[j];
        }
        bool diag = (kt == qt);
        #pragma unroll
        for (int i = 0; i < 4; ++i)
            #pragma unroll
            for (int j = 0; j < 4; ++j) {
                int r = ty * 4 + i, c = tx * 4 + j;
                float sv = acc[i][j];
                if (diag && c > r) sv = -INFINITY;
                Ss[r * 65 + c] = sv;
            }
        __syncthreads();

        // online softmax per row
        if (tid < 64) {
            int r = tid;
            float mt = mrow[r];
            for (int c = 0; c < 64; ++c) mt = fmaxf(mt, Ss[r * 65 + c]);
            float alpha = expf(mrow[r] - mt);
            float lnew = lrow[r] * alpha;
            for (int c = 0; c < 64; ++c) {
                float p = expf(Ss[r * 65 + c] - mt);
                Ss[r * 65 + c] = p;
                lnew += p;
            }
            mrow[r] = mt; lrow[r] = lnew;
            for (int c = 0; c < 64; ++c) Os[r * 65 + c] *= alpha;
        }
        __syncthreads();

        // O += P V
        float acc2[4][4] = {};
        #pragma unroll 8
        for (int j = 0; j < 64; ++j) {
            float pv[4], vv[4];
            #pragma unroll
            for (int i = 0; i < 4; ++i)  pv[i] = Ss[(ty * 4 + i) * 65 + j];
            #pragma unroll
            for (int jj = 0; jj < 4; ++jj) vv[jj] = Vs[j * 65 + tx * 4 + jj];
            #pragma unroll
            for (int i = 0; i < 4; ++i)
                #pragma unroll
                for (int jj = 0; jj < 4; ++jj) acc2[i][jj] += pv[i] * vv[jj];
        }
        #pragma unroll
        for (int i = 0; i < 4; ++i)
            #pragma unroll
            for (int jj = 0; jj < 4; ++jj)
                Os[(ty * 4 + i) * 65 + tx * 4 + jj] += acc2[i][jj];
        __syncthreads();
    }

    for (int i = tid; i < 64 * 64; i += 256) {
        int r = i >> 6, d = i & 63;
        g_att[((size_t)(b * CS + qt * 64 + r) * CH + h) * CHD + d] = Os[r * 65 + d] / lrow[r];
    }
}

// ---------------- router: logits -> softmax -> scores out + top-2 dispatch ----------------
__global__ void router_kernel(const float* __restrict__ Gw, float* __restrict__ scores_out) {
    int gtid = blockIdx.x * blockDim.x + threadIdx.x;
    int warp = gtid >> 5;
    int lane = threadIdx.x & 31;
    if (warp >= CT) return;
    const float* xr = g_hn + (size_t)warp * CD;
    float acc[CE] = {};
    for (int d = lane; d < CD; d += 32) {
        float xv = xr[d];
        const float* gr = Gw + (size_t)d * CE;
        #pragma unroll
        for (int e = 0; e < CE; ++e) acc[e] += xv * gr[e];
    }
    #pragma unroll
    for (int off = 16; off; off >>= 1)
        #pragma unroll
        for (int e = 0; e < CE; ++e) acc[e] += __shfl_down_sync(0xffffffffu, acc[e], off);

    if (lane == 0) {
        float mx = acc[0];
        #pragma unroll
        for (int e = 1; e < CE; ++e) mx = fmaxf(mx, acc[e]);
        float p[CE], sum = 0.f;
        #pragma unroll
        for (int e = 0; e < CE; ++e) { p[e] = expf(acc[e] - mx); sum += p[e]; }
        float inv = 1.f / sum;
        #pragma unroll
        for (int e = 0; e < CE; ++e) {
            p[e] *= inv;
            scores_out[(size_t)warp * CE + e] = p[e];
        }
        // top-2 (first-occurrence tie-break like lax.top_k)
        int e0 = 0; float b0 = p[0];
        #pragma unroll
        for (int e = 1; e < CE; ++e) if (p[e] > b0) { b0 = p[e]; e0 = e; }
        int e1 = -1; float b1 = -1.f;
        #pragma unroll
        for (int e = 0; e < CE; ++e) if (e != e0 && p[e] > b1) { b1 = p[e]; e1 = e; }
        float wsum = b0 + b1;
        float w0 = b0 / wsum, w1 = b1 / wsum;
        int p0 = atomicAdd(&g_cnt[e0], 1);
        g_tok[e0 * CT + p0] = warp; g_wsl[e0 * CT + p0] = w0;
        g_slot[warp * 2 + 0] = e0 * CT + p0;
        int p1 = atomicAdd(&g_cnt[e1], 1);
        g_tok[e1 * CT + p1] = warp; g_wsl[e1 * CT + p1] = w1;
        g_slot[warp * 2 + 1] = e1 * CT + p1;
    }
}

// ---------------- MoE up: H[slot, f] = w_slot * silu(x@w1_e) * (x@w3_e) ----------------
// grid: (F/64, 2048/64, E); weights folded in -> downstream is pure linear, no atomics needed
__global__ void moe_up_kernel(const float* __restrict__ W1, const float* __restrict__ W3) {
    int e = blockIdx.z;
    int cnt = g_cnt[e];
    int r0 = blockIdx.y * 64;
    if (r0 >= cnt) return;
    int f0 = blockIdx.x * 64;
    __shared__ float As[16 * 65], B1s[16 * 65], B3s[16 * 65];
    __shared__ int   toks[64];
    __shared__ float wrow[64];
    int tid = threadIdx.x, ty = tid >> 4, tx = tid & 15;
    if (tid < 64) {
        int rr = r0 + tid;
        bool ok = (rr < cnt);
        toks[tid] = ok ? g_tok[e * CT + rr] : 0;
        wrow[tid] = ok ? g_wsl[e * CT + rr] : 0.f;
    }
    __syncthreads();
    const float* w1e = W1 + (size_t)e * CD * CF;
    const float* w3e = W3 + (size_t)e * CD * CF;
    float acc1[4][4] = {}, acc3[4][4] = {};
    for (int k0 = 0; k0 < CD; k0 += 16) {
        #pragma unroll
        for (int it = 0; it < 4; ++it) {
            int r  = (tid >> 4) + it * 16;
            int kk = tid & 15;
            As[kk * 65 + r] = g_hn[(size_t)toks[r] * CD + k0 + kk];
        }
        #pragma unroll
        for (int it = 0; it < 4; ++it) {
            int kk = (tid >> 6) + it * 4;
            int c  = tid & 63;
            size_t off = (size_t)(k0 + kk) * CF + f0 + c;
            B1s[kk * 65 + c] = w1e[off];
            B3s[kk * 65 + c] = w3e[off];
        }
        __syncthreads();
        #pragma unroll
        for (int kk = 0; kk < 16; ++kk) {
            float a[4], b1v[4], b3v[4];
            #pragma unroll
            for (int i = 0; i < 4; ++i) a[i]   = As [kk * 65 + ty * 4 + i];
            #pragma unroll
            for (int j = 0; j < 4; ++j) { b1v[j] = B1s[kk * 65 + tx * 4 + j];
                                          b3v[j] = B3s[kk * 65 + tx * 4 + j]; }
            #pragma unroll
            for (int i = 0; i < 4; ++i)
                #pragma unroll
                for (int j = 0; j < 4; ++j) {
                    acc1[i][j] += a[i] * b1v[j];
                    acc3[i][j] += a[i] * b3v[j];
                }
        }
        __syncthreads();
    }
    #pragma unroll
    for (int i = 0; i < 4; ++i) {
        int rr = r0 + ty * 4 + i;
        if (rr < cnt) {
            float wv = wrow[ty * 4 + i];
            #pragma unroll
            for (int j = 0; j < 4; ++j) {
                float a1 = acc1[i][j];
                float hval = (a1 / (1.f + expf(-a1))) * acc3[i][j] * wv;
                g_hexp[((size_t)e * CT + rr) * CF + f0 + tx * 4 + j] = hval;
            }
        }
    }
}

// ---------------- MoE down: Y[slot, d] = H[slot,:] @ w2_e ----------------
__global__ void moe_down_kernel(const float* __restrict__ W2) {
    int e = blockIdx.z;
    int cnt = g_cnt[e];
    int r0 = blockIdx.y * 64;
    if (r0 >= cnt) return;
    int n0 = blockIdx.x * 64;
    __shared__ float As[16 * 65], Bs[16 * 65];
    int tid = threadIdx.x, ty = tid >> 4, tx = tid & 15;
    const float* Ae  = g_hexp + (size_t)e * CT * CF;
    const float* w2e = W2 + (size_t)e * CF * CD;
    float acc[4][4] = {};
    for (int k0 = 0; k0 < CF; k0 += 16) {
        #pragma unroll
        for (int it = 0; it < 4; ++it) {
            int r  = (tid >> 4) + it * 16;
            int kk = tid & 15;
            As[kk * 65 + r] = Ae[(size_t)(r0 + r) * CF + k0 + kk];
        }
        #pragma unroll
        for (int it = 0; it < 4; ++it) {
            int kk = (tid >> 6) + it * 4;
            int c  = tid & 63;
            Bs[kk * 65 + c] = w2e[(size_t)(k0 + kk) * CD + n0 + c];
        }
        __syncthreads();
        #pragma unroll
        for (int kk = 0; kk < 16; ++kk) {
            float a[4], bb[4];
            #pragma unroll
            for (int i = 0; i < 4; ++i) a[i]  = As[kk * 65 + ty * 4 + i];
            #pragma unroll
            for (int j = 0; j < 4; ++j) bb[j] = Bs[kk * 65 + tx * 4 + j];
            #pragma unroll
            for (int i = 0; i < 4; ++i)
                #pragma unroll
                for (int j = 0; j < 4; ++j) acc[i][j] += a[i] * bb[j];
        }
        __syncthreads();
    }
    #pragma unroll
    for (int i = 0; i < 4; ++i) {
        int rr = r0 + ty * 4 + i;
        if (rr < cnt) {
            #pragma unroll
            for (int j = 0; j < 4; ++j)
                g_y[((size_t)e * CT + rr) * CD + n0 + tx * 4 + j] = acc[i][j];
        }
    }
}

// ---------------- final combine: out = h1 + Y[slot0] + Y[slot1] ----------------
__global__ void combine_kernel(float* __restrict__ out) {
    int idx = blockIdx.x * 256 + threadIdx.x;
    if (idx >= CT * CD) return;
    int t = idx >> 10, d = idx & 1023;
    int s0 = g_slot[t * 2 + 0], s1 = g_slot[t * 2 + 1];
    out[idx] = g_h1[idx] + g_y[(size_t)s0 * CD + d] + g_y[(size_t)s1 * CD + d];
}

// ---------------- launcher ----------------
extern "C" void kernel_launch(void* const* d_in, const int* in_sizes, int n_in,
                              void* d_out, int out_size) {
    const float* hid = (const float*)d_in[0];
    const int*   pos = (const int*)  d_in[1];
    const float* ln1 = (const float*)d_in[3];
    const float* ln2 = (const float*)d_in[4];
    const float* wq  = (const float*)d_in[5];
    const float* wk  = (const float*)d_in[6];
    const float* wv  = (const float*)d_in[7];
    const float* wo  = (const float*)d_in[8];
    const float* gw  = (const float*)d_in[9];
    const float* w1  = (const float*)d_in[10];
    const float* w3  = (const float*)d_in[11];
    const float* w2  = (const float*)d_in[12];
    float* out        = (float*)d_out;
    float* out_scores = out + (size_t)CT * CD;

    float* xn;  cudaGetSymbolAddress((void**)&xn,  g_xn);
    float* q;   cudaGetSymbolAddress((void**)&q,   g_q);
    float* k;   cudaGetSymbolAddress((void**)&k,   g_k);
    float* v;   cudaGetSymbolAddress((void**)&v,   g_v);
    float* att; cudaGetSymbolAddress((void**)&att, g_att);
    float* h1;  cudaGetSymbolAddress((void**)&h1,  g_h1);
    float* hn;  cudaGetSymbolAddress((void**)&hn,  g_hn);
    int*   cnt; cudaGetSymbolAddress((void**)&cnt, g_cnt);

    cudaFuncSetAttribute(flash_kernel, cudaFuncAttributeMaxDynamicSharedMemorySize, FLASH_SMEM);

    // 1. rmsnorm1
    rmsnorm_kernel<<<CT, 256>>>(hid, ln1, xn);
    // 2-4. QKV projections
    gemm_kernel<<<dim3(CH * CHD / 64, CT / 64), 256>>>(xn, wq, nullptr, q, CT, CH * CHD, CD);
    gemm_kernel<<<dim3(CKV * CHD / 64, CT / 64), 256>>>(xn, wk, nullptr, k, CT, CKV * CHD, CD);
    gemm_kernel<<<dim3(CKV * CHD / 64, CT / 64), 256>>>(xn, wv, nullptr, v, CT, CKV * CHD, CD);
    // 5. RoPE
    {
        int total = CT * (CH + CKV) * 32;
        rope_kernel<<<(total + 255) / 256, 256>>>(pos);
    }
    // 6. flash attention
    flash_kernel<<<dim3(CB * CH, CS / 64), 256, FLASH_SMEM>>>();
    // 7. output projection + residual
    gemm_kernel<<<dim3(CD / 64, CT / 64), 256>>>(att, wo, hid, h1, CT, CD, CH * CHD);
    // 8. rmsnorm2
    rmsnorm_kernel<<<CT, 256>>>(h1, ln2, hn);
    // 9. reset dispatch counters
    cudaMemsetAsync(cnt, 0, CE * sizeof(int));
    // 10. router softmax + scores output + top-2 dispatch
    router_kernel<<<(CT * 32 + 255) / 256, 256>>>(gw, out_scores);
    // 11. MoE up (SwiGLU, routing weight folded in)
    moe_up_kernel<<<dim3(CF / 64, CT / 64, CE), 256>>>(w1, w3);
    // 12. MoE down
    moe_down_kernel<<<dim3(CD / 64, CT / 64, CE), 256>>>(w2);
    // 13. combine + residual -> d_out
    combine_kernel<<<(CT * CD + 255) / 256, 256>>>(out);
}

// round 2
// speedup vs baseline: 1.0024x; 1.0024x over previous
#include <cuda_runtime.h>
#include <math.h>

// ---------------- problem constants ----------------
constexpr int CB = 2, CS = 1024, CD = 1024;
constexpr int CH = 16, CKV = 4, CHD = 64;
constexpr int CE = 8, CTOPK = 2, CF = 2048;
constexpr int CT = CB * CS;              // 2048 tokens
constexpr float CEPS = 1e-6f;

// ---------------- scratch (static device memory; no allocs) ----------------
__device__ float g_xn [CT * CD];                 // rmsnorm1 out
__device__ float g_q  [CT * CH  * CHD];
__device__ float g_k  [CT * CKV * CHD];
__device__ float g_v  [CT * CKV * CHD];
__device__ float g_att[CT * CH  * CHD];
__device__ float g_h1 [CT * CD];                 // residual after attention
__device__ float g_hn [CT * CD];                 // rmsnorm2 out
__device__ int   g_cnt [CE];
__device__ int   g_tok [CE * CT];
__device__ float g_wsl [CE * CT];
__device__ int   g_slot[CT * CTOPK];
__device__ float g_hexp[(size_t)CE * CT * CF];   // 134 MB: weighted SwiGLU activations
__device__ float g_y   [(size_t)CE * CT * CD];   // 67 MB: per-slot expert outputs

// ---------------- RMSNorm ----------------
__global__ void rmsnorm_kernel(const float* __restrict__ x, const float* __restrict__ w,
                               float* __restrict__ out) {
    int t = blockIdx.x;
    const float* xr = x + (size_t)t * CD;
    float ss = 0.f;
    for (int d = threadIdx.x; d < CD; d += 256) { float v = xr[d]; ss += v * v; }
    __shared__ float red[256];
    red[threadIdx.x] = ss;
    __syncthreads();
    for (int s = 128; s > 0; s >>= 1) {
        if (threadIdx.x < s) red[threadIdx.x] += red[threadIdx.x + s];
        __syncthreads();
    }
    __shared__ float rinv;
    if (threadIdx.x == 0) rinv = rsqrtf(red[0] * (1.f / CD) + CEPS);
    __syncthreads();
    float* orow = out + (size_t)t * CD;
    for (int d = threadIdx.x; d < CD; d += 256) orow[d] = xr[d] * rinv * w[d];
}

// ---------------- generic tiled GEMM: C[M,N] = A[M,K] @ B[K,N] (+ Res) ----------------
// BM=BN=64, BK=16, 256 threads, 4x4 micro-tile. M,N,K multiples of 64/16 here.
__global__ void gemm_kernel(const float* __restrict__ A, const float* __restrict__ Bw,
                            const float* __restrict__ Res, float* __restrict__ C,
                            int M, int N, int K) {
    __shared__ float As[16 * 65];   // As[kk][row]
    __shared__ float Bs[16 * 65];   // Bs[kk][col]
    int m0 = blockIdx.y * 64, n0 = blockIdx.x * 64;
    int tid = threadIdx.x, ty = tid >> 4, tx = tid & 15;
    float acc[4][4] = {};
    for (int k0 = 0; k0 < K; k0 += 16) {
        #pragma unroll
        for (int it = 0; it < 4; ++it) {
            int r  = (tid >> 4) + it * 16;
            int kk = tid & 15;
            As[kk * 65 + r] = A[(size_t)(m0 + r) * K + k0 + kk];
        }
        #pragma unroll
        for (int it = 0; it < 4; ++it) {
            int kk = (tid >> 6) + it * 4;
            int c  = tid & 63;
            Bs[kk * 65 + c] = Bw[(size_t)(k0 + kk) * N + n0 + c];
        }
        __syncthreads();
        #pragma unroll
        for (int kk = 0; kk < 16; ++kk) {
            float a[4], bb[4];
            #pragma unroll
            for (int i = 0; i < 4; ++i) a[i]  = As[kk * 65 + ty * 4 + i];
            #pragma unroll
            for (int j = 0; j < 4; ++j) bb[j] = Bs[kk * 65 + tx * 4 + j];
            #pragma unroll
            for (int i = 0; i < 4; ++i)
                #pragma unroll
                for (int j = 0; j < 4; ++j) acc[i][j] += a[i] * bb[j];
        }
        __syncthreads();
    }
    #pragma unroll
    for (int i = 0; i < 4; ++i)
        #pragma unroll
        for (int j = 0; j < 4; ++j) {
            size_t idx = (size_t)(m0 + ty * 4 + i) * N + n0 + tx * 4 + j;
            float r = Res ? Res[idx] : 0.f;
            C[idx] = acc[i][j] + r;
        }
}

// ---------------- RoPE (q and k, in place) ----------------
__global__ void rope_kernel(const int* __restrict__ pos_ids) {
    int idx = blockIdx.x * 256 + threadIdx.x;
    const int nq = CT * CH * 32;
    const int nk = CT * CKV * 32;
    if (idx >= nq + nk) return;
    float* base;
    int i, t;
    if (idx < nq) {
        i = idx & 31; int th = idx >> 5; int h = th % CH; t = th / CH;
        base = g_q + ((size_t)t * CH + h) * CHD;
    } else {
        int id2 = idx - nq;
        i = id2 & 31; int th = id2 >> 5; int h = th % CKV; t = th / CKV;
        base = g_k + ((size_t)t * CKV + h) * CHD;
    }
    float p = (float)pos_ids[t];
    float freq = expf(-(2.f * i / (float)CHD) * logf(10000.f));
    float ang = p * freq;
    float c = cosf(ang), s = sinf(ang);
    float x0 = base[i], x1 = base[i + 32];
    base[i]      = x0 * c - x1 * s;
    base[i + 32] = x1 * c + x0 * s;
}

// ---------------- flash-style causal attention ----------------
// grid: (B*H, S/64); block 256 threads; dynamic smem: 5 tiles 64x65 + m,l
constexpr int FLASH_SMEM = (5 * 64 * 65 + 128) * 4;
__global__ void flash_kernel() {
    extern __shared__ float sm[];
    float* Qs = sm;
    float* Ks = Qs + 64 * 65;
    float* Vs = Ks + 64 * 65;
    float* Ss = Vs + 64 * 65;
    float* Os = Ss + 64 * 65;
    float* mrow = Os + 64 * 65;
    float* lrow = mrow + 64;

    int bh = blockIdx.x, qt = blockIdx.y;
    int b = bh / CH, h = bh % CH, kvh = h / (CH / CKV);
    int tid = threadIdx.x, ty = tid >> 4, tx = tid & 15;

    for (int i = tid; i < 64 * 64; i += 256) {
        int r = i >> 6, d = i & 63;
        Qs[r * 65 + d] = g_q[((size_t)(b * CS + qt * 64 + r) * CH + h) * CHD + d] * 0.125f;
        Os[r * 65 + d] = 0.f;
    }
    if (tid < 64) { mrow[tid] = -INFINITY; lrow[tid] = 0.f; }
    __syncthreads();

    for (int kt = 0; kt <= qt; ++kt) {
        for (int i = tid; i < 64 * 64; i += 256) {
            int r = i >> 6, d = i & 63;
            size_t jb = (size_t)(b * CS + kt * 64 + r) * CKV + kvh;
            Ks[r * 65 + d] = g_k[jb * CHD + d];
            Vs[r * 65 + d] = g_v[jb * CHD + d];
        }
        __syncthreads();

        // S = Q K^T
        float acc[4][4] = {};
        #pragma unroll 8
        for (int kk = 0; kk < 64; ++kk) {
            float qa[4], kb[4];
            #pragma unroll
            for (int i = 0; i < 4; ++i) qa[i] = Qs[(ty * 4 + i) * 65 + kk];
            #pragma unroll
            for (int j = 0; j < 4; ++j) kb[j] = Ks[(tx * 4 + j) * 65 + kk];
            #pragma unroll
            for (int i = 0; i < 4; ++i)
                #pragma unroll
                for (int j = 0; j < 4; ++j) acc[i][j] += qa[i] * kb[j];
        }
        bool diag = (kt == qt);
        #pragma unroll
        for (int i = 0; i < 4; ++i)
            #pragma unroll
            for (int j = 0; j < 4; ++j) {
                int r = ty * 4 + i, c = tx * 4 + j;
                float sv = acc[i][j];
                if (diag && c > r) sv = -INFINITY;
                Ss[r * 65 + c] = sv;
            }
        __syncthreads();

        // online softmax per row
        if (tid < 64) {
            int r = tid;
            float mt = mrow[r];
            for (int c = 0; c < 64; ++c) mt = fmaxf(mt, Ss[r * 65 + c]);
            float alpha = expf(mrow[r] - mt);
            float lnew = lrow[r] * alpha;
            for (int c = 0; c < 64; ++c) {
                float p = expf(Ss[r * 65 + c] - mt);
                Ss[r * 65 + c] = p;
                lnew += p;
            }
            mrow[r] = mt; lrow[r] = lnew;
            for (int c = 0; c < 64; ++c) Os[r * 65 + c] *= alpha;
        }
        __syncthreads();

        // O += P V
        float acc2[4][4] = {};
        #pragma unroll 8
        for (int j = 0; j < 64; ++j) {
            float pv[4], vv[4];
            #pragma unroll
            for (int i = 0; i < 4; ++i)  pv[i] = Ss[(ty * 4 + i) * 65 + j];
            #pragma unroll
            for (int jj = 0; jj < 4; ++jj) vv[jj] = Vs[j * 65 + tx * 4 + jj];
            #pragma unroll
            for (int i = 0; i < 4; ++i)
                #pragma unroll
                for (int jj = 0; jj < 4; ++jj) acc2[i][jj] += pv[i] * vv[jj];
        }
        #pragma unroll
        for (int i = 0; i < 4; ++i)
            #pragma unroll
            for (int jj = 0; jj < 4; ++jj)
                Os[(ty * 4 + i) * 65 + tx * 4 + jj] += acc2[i][jj];
        __syncthreads();
    }

    for (int i = tid; i < 64 * 64; i += 256) {
        int r = i >> 6, d = i & 63;
        g_att[((size_t)(b * CS + qt * 64 + r) * CH + h) * CHD + d] = Os[r * 65 + d] / lrow[r];
    }
}

// ---------------- router: logits -> softmax -> scores out + top-2 dispatch ----------------
__global__ void router_kernel(const float* __restrict__ Gw, float* __restrict__ scores_out) {
    int gtid = blockIdx.x * blockDim.x + threadIdx.x;
    int warp = gtid >> 5;
    int lane = threadIdx.x & 31;
    if (warp >= CT) return;
    const float* xr = g_hn + (size_t)warp * CD;
    float acc[CE] = {};
    for (int d = lane; d < CD; d += 32) {
        float xv = xr[d];
        const float* gr = Gw + (size_t)d * CE;
        #pragma unroll
        for (int e = 0; e < CE; ++e) acc[e] += xv * gr[e];
    }
    #pragma unroll
    for (int off = 16; off; off >>= 1)
        #pragma unroll
        for (int e = 0; e < CE; ++e) acc[e] += __shfl_down_sync(0xffffffffu, acc[e], off);

    if (lane == 0) {
        float mx = acc[0];
        #pragma unroll
        for (int e = 1; e < CE; ++e) mx = fmaxf(mx, acc[e]);
        float p[CE], sum = 0.f;
        #pragma unroll
        for (int e = 0; e < CE; ++e) { p[e] = expf(acc[e] - mx); sum += p[e]; }
        float inv = 1.f / sum;
        #pragma unroll
        for (int e = 0; e < CE; ++e) {
            p[e] *= inv;
            scores_out[(size_t)warp * CE + e] = p[e];
        }
        // top-2 (first-occurrence tie-break like lax.top_k)
        int e0 = 0; float b0 = p[0];
        #pragma unroll
        for (int e = 1; e < CE; ++e) if (p[e] > b0) { b0 = p[e]; e0 = e; }
        int e1 = -1; float b1 = -1.f;
        #pragma unroll
        for (int e = 0; e < CE; ++e) if (e != e0 && p[e] > b1) { b1 = p[e]; e1 = e; }
        float wsum = b0 + b1;
        float w0 = b0 / wsum, w1 = b1 / wsum;
        int p0 = atomicAdd(&g_cnt[e0], 1);
        g_tok[e0 * CT + p0] = warp; g_wsl[e0 * CT + p0] = w0;
        g_slot[warp * 2 + 0] = e0 * CT + p0;
        int p1 = atomicAdd(&g_cnt[e1], 1);
        g_tok[e1 * CT + p1] = warp; g_wsl[e1 * CT + p1] = w1;
        g_slot[warp * 2 + 1] = e1 * CT + p1;
    }
}

// ---------------- MoE up: H[slot, f] = w_slot * silu(x@w1_e) * (x@w3_e) ----------------
// grid: (F/64, 2048/64, E); weights folded in -> downstream is pure linear, no atomics needed
__global__ void moe_up_kernel(const float* __restrict__ W1, const float* __restrict__ W3) {
    int e = blockIdx.z;
    int cnt = g_cnt[e];
    int r0 = blockIdx.y * 64;
    if (r0 >= cnt) return;
    int f0 = blockIdx.x * 64;
    __shared__ float As[16 * 65], B1s[16 * 65], B3s[16 * 65];
    __shared__ int   toks[64];
    __shared__ float wrow[64];
    int tid = threadIdx.x, ty = tid >> 4, tx = tid & 15;
    if (tid < 64) {
        int rr = r0 + tid;
        bool ok = (rr < cnt);
        toks[tid] = ok ? g_tok[e * CT + rr] : 0;
        wrow[tid] = ok ? g_wsl[e * CT + rr] : 0.f;
    }
    __syncthreads();
    const float* w1e = W1 + (size_t)e * CD * CF;
    const float* w3e = W3 + (size_t)e * CD * CF;
    float acc1[4][4] = {}, acc3[4][4] = {};
    for (int k0 = 0; k0 < CD; k0 += 16) {
        #pragma unroll
        for (int it = 0; it < 4; ++it) {
            int r  = (tid >> 4) + it * 16;
            int kk = tid & 15;
            As[kk * 65 + r] = g_hn[(size_t)toks[r] * CD + k0 + kk];
        }
        #pragma unroll
        for (int it = 0; it < 4; ++it) {
            int kk = (tid >> 6) + it * 4;
            int c  = tid & 63;
            size_t off = (size_t)(k0 + kk) * CF + f0 + c;
            B1s[kk * 65 + c] = w1e[off];
            B3s[kk * 65 + c] = w3e[off];
        }
        __syncthreads();
        #pragma unroll
        for (int kk = 0; kk < 16; ++kk) {
            float a[4], b1v[4], b3v[4];
            #pragma unroll
            for (int i = 0; i < 4; ++i) a[i]   = As [kk * 65 + ty * 4 + i];
            #pragma unroll
            for (int j = 0; j < 4; ++j) { b1v[j] = B1s[kk * 65 + tx * 4 + j];
                                          b3v[j] = B3s[kk * 65 + tx * 4 + j]; }
            #pragma unroll
            for (int i = 0; i < 4; ++i)
                #pragma unroll
                for (int j = 0; j < 4; ++j) {
                    acc1[i][j] += a[i] * b1v[j];
                    acc3[i][j] += a[i] * b3v[j];
                }
        }
        __syncthreads();
    }
    #pragma unroll
    for (int i = 0; i < 4; ++i) {
        int rr = r0 + ty * 4 + i;
        if (rr < cnt) {
            float wv = wrow[ty * 4 + i];
            #pragma unroll
            for (int j = 0; j < 4; ++j) {
                float a1 = acc1[i][j];
                float hval = (a1 / (1.f + expf(-a1))) * acc3[i][j] * wv;
                g_hexp[((size_t)e * CT + rr) * CF + f0 + tx * 4 + j] = hval;
            }
        }
    }
}

// ---------------- MoE down: Y[slot, d] = H[slot,:] @ w2_e ----------------
__global__ void moe_down_kernel(const float* __restrict__ W2) {
    int e = blockIdx.z;
    int cnt = g_cnt[e];
    int r0 = blockIdx.y * 64;
    if (r0 >= cnt) return;
    int n0 = blockIdx.x * 64;
    __shared__ float As[16 * 65], Bs[16 * 65];
    int tid = threadIdx.x, ty = tid >> 4, tx = tid & 15;
    const float* Ae  = g_hexp + (size_t)e * CT * CF;
    const float* w2e = W2 + (size_t)e * CF * CD;
    float acc[4][4] = {};
    for (int k0 = 0; k0 < CF; k0 += 16) {
        #pragma unroll
        for (int it = 0; it < 4; ++it) {
            int r  = (tid >> 4) + it * 16;
            int kk = tid & 15;
            As[kk * 65 + r] = Ae[(size_t)(r0 + r) * CF + k0 + kk];
        }
        #pragma unroll
        for (int it = 0; it < 4; ++it) {
            int kk = (tid >> 6) + it * 4;
            int c  = tid & 63;
            Bs[kk * 65 + c] = w2e[(size_t)(k0 + kk) * CD + n0 + c];
        }
        __syncthreads();
        #pragma unroll
        for (int kk = 0; kk < 16; ++kk) {
            float a[4], bb[4];
            #pragma unroll
            for (int i = 0; i < 4; ++i) a[i]  = As[kk * 65 + ty * 4 + i];
            #pragma unroll
            for (int j = 0; j < 4; ++j) bb[j] = Bs[kk * 65 + tx * 4 + j];
            #pragma unroll
            for (int i = 0; i < 4; ++i)
                #pragma unroll
                for (int j = 0; j < 4; ++j) acc[i][j] += a[i] * bb[j];
        }
        __syncthreads();
    }
    #pragma unroll
    for (int i = 0; i < 4; ++i) {
        int rr = r0 + ty * 4 + i;
        if (rr < cnt) {
            #pragma unroll
            for (int j = 0; j < 4; ++j)
                g_y[((size_t)e * CT + rr) * CD + n0 + tx * 4 + j] = acc[i][j];
        }
    }
}

// ---------------- final combine: out = h1 + Y[slot0] + Y[slot1] ----------------
__global__ void combine_kernel(float* __restrict__ out) {
    int idx = blockIdx.x * 256 + threadIdx.x;
    if (idx >= CT * CD) return;
    int t = idx >> 10, d = idx & 1023;
    int s0 = g_slot[t * 2 + 0], s1 = g_slot[t * 2 + 1];
    out[idx] = g_h1[idx] + g_y[(size_t)s0 * CD + d] + g_y[(size_t)s1 * CD + d];
}

// ---------------- launcher ----------------
extern "C" void kernel_launch(void* const* d_in, const int* in_sizes, int n_in,
                              void* d_out, int out_size) {
    const float* hid = (const float*)d_in[0];
    const int*   pos = (const int*)  d_in[1];
    const float* ln1 = (const float*)d_in[3];
    const float* ln2 = (const float*)d_in[4];
    const float* wq  = (const float*)d_in[5];
    const float* wk  = (const float*)d_in[6];
    const float* wv  = (const float*)d_in[7];
    const float* wo  = (const float*)d_in[8];
    const float* gw  = (const float*)d_in[9];
    const float* w1  = (const float*)d_in[10];
    const float* w3  = (const float*)d_in[11];
    const float* w2  = (const float*)d_in[12];
    float* out        = (float*)d_out;
    float* out_scores = out + (size_t)CT * CD;

    float* xn;  cudaGetSymbolAddress((void**)&xn,  g_xn);
    float* q;   cudaGetSymbolAddress((void**)&q,   g_q);
    float* k;   cudaGetSymbolAddress((void**)&k,   g_k);
    float* v;   cudaGetSymbolAddress((void**)&v,   g_v);
    float* att; cudaGetSymbolAddress((void**)&att, g_att);
    float* h1;  cudaGetSymbolAddress((void**)&h1,  g_h1);
    float* hn;  cudaGetSymbolAddress((void**)&hn,  g_hn);
    int*   cnt; cudaGetSymbolAddress((void**)&cnt, g_cnt);

    cudaFuncSetAttribute(flash_kernel, cudaFuncAttributeMaxDynamicSharedMemorySize, FLASH_SMEM);

    // 1. rmsnorm1
    rmsnorm_kernel<<<CT, 256>>>(hid, ln1, xn);
    // 2-4. QKV projections
    gemm_kernel<<<dim3(CH * CHD / 64, CT / 64), 256>>>(xn, wq, nullptr, q, CT, CH * CHD, CD);
    gemm_kernel<<<dim3(CKV * CHD / 64, CT / 64), 256>>>(xn, wk, nullptr, k, CT, CKV * CHD, CD);
    gemm_kernel<<<dim3(CKV * CHD / 64, CT / 64), 256>>>(xn, wv, nullptr, v, CT, CKV * CHD, CD);
    // 5. RoPE
    {
        int total = CT * (CH + CKV) * 32;
        rope_kernel<<<(total + 255) / 256, 256>>>(pos);
    }
    // 6. flash attention
    flash_kernel<<<dim3(CB * CH, CS / 64), 256, FLASH_SMEM>>>();
    // 7. output projection + residual
    gemm_kernel<<<dim3(CD / 64, CT / 64), 256>>>(att, wo, hid, h1, CT, CD, CH * CHD);
    // 8. rmsnorm2
    rmsnorm_kernel<<<CT, 256>>>(h1, ln2, hn);
    // 9. reset dispatch counters
    cudaMemsetAsync(cnt, 0, CE * sizeof(int));
    // 10. router softmax + scores output + top-2 dispatch
    router_kernel<<<(CT * 32 + 255) / 256, 256>>>(gw, out_scores);
    // 11. MoE up (SwiGLU, routing weight folded in)
    moe_up_kernel<<<dim3(CF / 64, CT / 64, CE), 256>>>(w1, w3);
    // 12. MoE down
    moe_down_kernel<<<dim3(CD / 64, CT / 64, CE), 256>>>(w2);
    // 13. combine + residual -> d_out
    combine_kernel<<<(CT * CD + 255) / 256, 256>>>(out);
}

// round 3
// speedup vs baseline: 2.0651x; 2.0602x over previous
#include <cuda_runtime.h>
#include <math.h>
#include <stdint.h>

constexpr int CB = 2, CS = 1024, CD = 1024;
constexpr int CH = 16, CKV = 4, CHD = 64;
constexpr int CE = 8, CF = 2048;
constexpr int CT = CB * CS;
constexpr float CEPS = 1e-6f;

__device__ float g_xn [CT * CD];
__device__ float g_q  [CT * CH  * CHD];
__device__ float g_k  [CT * CKV * CHD];
__device__ float g_v  [CT * CKV * CHD];
__device__ float g_att[CT * CH  * CHD];
__device__ float g_h1 [CT * CD];
__device__ float g_hn [CT * CD];
__device__ int   g_cnt [CE];
__device__ int   g_tok [CE * CT];
__device__ float g_wsl [CE * CT];
__device__ int   g_slot[CT * 2];
__device__ float g_hexp[(size_t)CE * CT * CF];
__device__ float g_y   [(size_t)CE * CT * CD];

__device__ __forceinline__ float to_tf32(float x) {
    float r; asm("cvt.rna.tf32.f32 %0, %1;" : "=f"(r) : "f"(x)); return r;
}
#define U32(x) __float_as_uint(x)
#define MMA(c, a, b0, b1) \
    asm volatile("mma.sync.aligned.m16n8k8.row.col.f32.tf32.tf32.f32 " \
        "{%0,%1,%2,%3}, {%4,%5,%6,%7}, {%8,%9}, {%0,%1,%2,%3};" \
        : "+f"((c)[0]), "+f"((c)[1]), "+f"((c)[2]), "+f"((c)[3]) \
        : "r"((a)[0]), "r"((a)[1]), "r"((a)[2]), "r"((a)[3]), "r"(b0), "r"(b1))

// ---------------- RMSNorm ----------------
__global__ void rmsnorm_kernel(const float* __restrict__ x, const float* __restrict__ w,
                               float* __restrict__ out) {
    int t = blockIdx.x;
    const float* xr = x + (size_t)t * CD;
    float ss = 0.f;
    for (int d = threadIdx.x; d < CD; d += 256) { float v = xr[d]; ss += v * v; }
    __shared__ float red[256];
    red[threadIdx.x] = ss;
    __syncthreads();
    for (int s = 128; s > 0; s >>= 1) {
        if (threadIdx.x < s) red[threadIdx.x] += red[threadIdx.x + s];
        __syncthreads();
    }
    __shared__ float rinv;
    if (threadIdx.x == 0) rinv = rsqrtf(red[0] * (1.f / CD) + CEPS);
    __syncthreads();
    float* orow = out + (size_t)t * CD;
    for (int d = threadIdx.x; d < CD; d += 256) orow[d] = xr[d] * rinv * w[d];
}

// ---------------- TF32 MMA GEMM: C[M,N] = A@B (+Res). BM=128,BN=64,BK=16 ----------------
template<bool TRIPLE>
__global__ __launch_bounds__(256) void mma_gemm(
    const float* __restrict__ A, const float* __restrict__ B,
    const float* __restrict__ Res, float* __restrict__ C, int M, int N, int K)
{
    __shared__ float Ah[16][136], Bh[16][72];
    __shared__ float Al[TRIPLE ? 16 : 1][TRIPLE ? 136 : 1];
    __shared__ float Bl[TRIPLE ? 16 : 1][TRIPLE ? 72 : 1];
    int tid = threadIdx.x, lane = tid & 31, wid = tid >> 5, grp = lane >> 2, tig = lane & 3;
    int wm = (wid >> 1) * 32, wn = (wid & 1) * 32;
    int m0 = blockIdx.y * 128, n0 = blockIdx.x * 64;
    int ar = tid >> 1, akq = (tid & 1) * 8;
    int bk = tid >> 4, bc = (tid & 15) * 4;
    float c[2][4][4] = {};
    for (int k0 = 0; k0 < K; k0 += 16) {
        float4 a0 = *(const float4*)&A[(size_t)(m0 + ar) * K + k0 + akq];
        float4 a1 = *(const float4*)&A[(size_t)(m0 + ar) * K + k0 + akq + 4];
        float4 bv = *(const float4*)&B[(size_t)(k0 + bk) * N + n0 + bc];
        __syncthreads();
        const float* p0 = (const float*)&a0; const float* p1 = (const float*)&a1;
        const float* pb = (const float*)&bv;
        #pragma unroll
        for (int j = 0; j < 4; ++j) {
            float h0 = to_tf32(p0[j]); Ah[akq + j][ar] = h0;
            float h1 = to_tf32(p1[j]); Ah[akq + 4 + j][ar] = h1;
            float hb = to_tf32(pb[j]); Bh[bk][bc + j] = hb;
            if constexpr (TRIPLE) {
                Al[akq + j][ar] = to_tf32(p0[j] - h0);
                Al[akq + 4 + j][ar] = to_tf32(p1[j] - h1);
                Bl[bk][bc + j] = to_tf32(pb[j] - hb);
            }
        }
        __syncthreads();
        #pragma unroll
        for (int ks = 0; ks < 16; ks += 8) {
            uint32_t ah[2][4], al[2][4];
            #pragma unroll
            for (int i = 0; i < 2; ++i) {
                int r = wm + 16 * i;
                ah[i][0] = U32(Ah[ks + tig][r + grp]);     ah[i][1] = U32(Ah[ks + tig][r + grp + 8]);
                ah[i][2] = U32(Ah[ks + tig + 4][r + grp]); ah[i][3] = U32(Ah[ks + tig + 4][r + grp + 8]);
                if constexpr (TRIPLE) {
                    al[i][0] = U32(Al[ks + tig][r + grp]);     al[i][1] = U32(Al[ks + tig][r + grp + 8]);
                    al[i][2] = U32(Al[ks + tig + 4][r + grp]); al[i][3] = U32(Al[ks + tig + 4][r + grp + 8]);
                }
            }
            #pragma unroll
            for (int j = 0; j < 4; ++j) {
                int cc = wn + 8 * j + grp;
                uint32_t bh0 = U32(Bh[ks + tig][cc]), bh1 = U32(Bh[ks + tig + 4][cc]);
                #pragma unroll
                for (int i = 0; i < 2; ++i) MMA(c[i][j], ah[i], bh0, bh1);
                if constexpr (TRIPLE) {
                    uint32_t bl0 = U32(Bl[ks + tig][cc]), bl1 = U32(Bl[ks + tig + 4][cc]);
                    #pragma unroll
                    for (int i = 0; i < 2; ++i) { MMA(c[i][j], ah[i], bl0, bl1); MMA(c[i][j], al[i], bh0, bh1); }
                }
            }
        }
    }
    #pragma unroll
    for (int i = 0; i < 2; ++i) {
        int r = m0 + wm + 16 * i + grp;
        #pragma unroll
        for (int j = 0; j < 4; ++j) {
            int cc = n0 + wn + 8 * j + 2 * tig;
            size_t i0 = (size_t)r * N + cc, i1 = (size_t)(r + 8) * N + cc;
            C[i0]     = c[i][j][0] + (Res ? Res[i0] : 0.f);
            C[i0 + 1] = c[i][j][1] + (Res ? Res[i0 + 1] : 0.f);
            C[i1]     = c[i][j][2] + (Res ? Res[i1] : 0.f);
            C[i1 + 1] = c[i][j][3] + (Res ? Res[i1 + 1] : 0.f);
        }
    }
}

// ---------------- RoPE ----------------
__global__ void rope_kernel(const int* __restrict__ pos_ids) {
    int idx = blockIdx.x * 256 + threadIdx.x;
    const int nq = CT * CH * 32, nk = CT * CKV * 32;
    if (idx >= nq + nk) return;
    float* base; int i, t;
    if (idx < nq) {
        i = idx & 31; int th = idx >> 5; int h = th % CH; t = th / CH;
        base = g_q + ((size_t)t * CH + h) * CHD;
    } else {
        int id2 = idx - nq;
        i = id2 & 31; int th = id2 >> 5; int h = th % CKV; t = th / CKV;
        base = g_k + ((size_t)t * CKV + h) * CHD;
    }
    float p = (float)pos_ids[t];
    float freq = expf(-(2.f * i / (float)CHD) * logf(10000.f));
    float ang = p * freq, c = cosf(ang), s = sinf(ang);
    float x0 = base[i], x1 = base[i + 32];
    base[i] = x0 * c - x1 * s;
    base[i + 32] = x1 * c + x0 * s;
}

// ---------------- flash attention (scalar fp32, unchanged) ----------------
constexpr int FLASH_SMEM = (5 * 64 * 65 + 128) * 4;
__global__ void flash_kernel() {
    extern __shared__ float sm[];
    float* Qs = sm;
    float* Ks = Qs + 64 * 65;
    float* Vs = Ks + 64 * 65;
    float* Ss = Vs + 64 * 65;
    float* Os = Ss + 64 * 65;
    float* mrow = Os + 64 * 65;
    float* lrow = mrow + 64;
    int bh = blockIdx.x, qt = blockIdx.y;
    int b = bh / CH, h = bh % CH, kvh = h / (CH / CKV);
    int tid = threadIdx.x, ty = tid >> 4, tx = tid & 15;
    for (int i = tid; i < 64 * 64; i += 256) {
        int r = i >> 6, d = i & 63;
        Qs[r * 65 + d] = g_q[((size_t)(b * CS + qt * 64 + r) * CH + h) * CHD + d] * 0.125f;
        Os[r * 65 + d] = 0.f;
    }
    if (tid < 64) { mrow[tid] = -INFINITY; lrow[tid] = 0.f; }
    __syncthreads();
    for (int kt = 0; kt <= qt; ++kt) {
        for (int i = tid; i < 64 * 64; i += 256) {
            int r = i >> 6, d = i & 63;
            size_t jb = (size_t)(b * CS + kt * 64 + r) * CKV + kvh;
            Ks[r * 65 + d] = g_k[jb * CHD + d];
            Vs[r * 65 + d] = g_v[jb * CHD + d];
        }
        __syncthreads();
        float acc[4][4] = {};
        #pragma unroll 8
        for (int kk = 0; kk < 64; ++kk) {
            float qa[4], kb[4];
            #pragma unroll
            for (int i = 0; i < 4; ++i) qa[i] = Qs[(ty * 4 + i) * 65 + kk];
            #pragma unroll
            for (int j = 0; j < 4; ++j) kb[j] = Ks[(tx * 4 + j) * 65 + kk];
            #pragma unroll
            for (int i = 0; i < 4; ++i)
                #pragma unroll
                for (int j = 0; j < 4; ++j) acc[i][j] += qa[i] * kb[j];
        }
        bool diag = (kt == qt);
        #pragma unroll
        for (int i = 0; i < 4; ++i)
            #pragma unroll
            for (int j = 0; j < 4; ++j) {
                int r = ty * 4 + i, cc = tx * 4 + j;
                float sv = acc[i][j];
                if (diag && cc > r) sv = -INFINITY;
                Ss[r * 65 + cc] = sv;
            }
        __syncthreads();
        if (tid < 64) {
            int r = tid;
            float mt = mrow[r];
            for (int cc = 0; cc < 64; ++cc) mt = fmaxf(mt, Ss[r * 65 + cc]);
            float alpha = expf(mrow[r] - mt);
            float lnew = lrow[r] * alpha;
            for (int cc = 0; cc < 64; ++cc) {
                float p = expf(Ss[r * 65 + cc] - mt);
                Ss[r * 65 + cc] = p;
                lnew += p;
            }
            mrow[r] = mt; lrow[r] = lnew;
            for (int cc = 0; cc < 64; ++cc) Os[r * 65 + cc] *= alpha;
        }
        __syncthreads();
        float acc2[4][4] = {};
        #pragma unroll 8
        for (int j = 0; j < 64; ++j) {
            float pv[4], vv[4];
            #pragma unroll
            for (int i = 0; i < 4; ++i)  pv[i] = Ss[(ty * 4 + i) * 65 + j];
            #pragma unroll
            for (int jj = 0; jj < 4; ++jj) vv[jj] = Vs[j * 65 + tx * 4 + jj];
            #pragma unroll
            for (int i = 0; i < 4; ++i)
                #pragma unroll
                for (int jj = 0; jj < 4; ++jj) acc2[i][jj] += pv[i] * vv[jj];
        }
        #pragma unroll
        for (int i = 0; i < 4; ++i)
            #pragma unroll
            for (int jj = 0; jj < 4; ++jj)
                Os[(ty * 4 + i) * 65 + tx * 4 + jj] += acc2[i][jj];
        __syncthreads();
    }
    for (int i = tid; i < 64 * 64; i += 256) {
        int r = i >> 6, d = i & 63;
        g_att[((size_t)(b * CS + qt * 64 + r) * CH + h) * CHD + d] = Os[r * 65 + d] / lrow[r];
    }
}

// ---------------- router ----------------
__global__ void router_kernel(const float* __restrict__ Gw, float* __restrict__ scores_out) {
    int gtid = blockIdx.x * blockDim.x + threadIdx.x;
    int warp = gtid >> 5, lane = threadIdx.x & 31;
    if (warp >= CT) return;
    const float* xr = g_hn + (size_t)warp * CD;
    float acc[CE] = {};
    for (int d = lane; d < CD; d += 32) {
        float xv = xr[d];
        const float* gr = Gw + (size_t)d * CE;
        #pragma unroll
        for (int e = 0; e < CE; ++e) acc[e] += xv * gr[e];
    }
    #pragma unroll
    for (int off = 16; off; off >>= 1)
        #pragma unroll
        for (int e = 0; e < CE; ++e) acc[e] += __shfl_down_sync(0xffffffffu, acc[e], off);
    if (lane == 0) {
        float mx = acc[0];
        #pragma unroll
        for (int e = 1; e < CE; ++e) mx = fmaxf(mx, acc[e]);
        float p[CE], sum = 0.f;
        #pragma unroll
        for (int e = 0; e < CE; ++e) { p[e] = expf(acc[e] - mx); sum += p[e]; }
        float inv = 1.f / sum;
        #pragma unroll
        for (int e = 0; e < CE; ++e) { p[e] *= inv; scores_out[(size_t)warp * CE + e] = p[e]; }
        int e0 = 0; float b0 = p[0];
        #pragma unroll
        for (int e = 1; e < CE; ++e) if (p[e] > b0) { b0 = p[e]; e0 = e; }
        int e1 = -1; float b1 = -1.f;
        #pragma unroll
        for (int e = 0; e < CE; ++e) if (e != e0 && p[e] > b1) { b1 = p[e]; e1 = e; }
        float wsum = b0 + b1;
        int p0 = atomicAdd(&g_cnt[e0], 1);
        g_tok[e0 * CT + p0] = warp; g_wsl[e0 * CT + p0] = b0 / wsum;
        g_slot[warp * 2 + 0] = e0 * CT + p0;
        int p1 = atomicAdd(&g_cnt[e1], 1);
        g_tok[e1 * CT + p1] = warp; g_wsl[e1 * CT + p1] = b1 / wsum;
        g_slot[warp * 2 + 1] = e1 * CT + p1;
    }
}

// ---------------- MoE up: 1xTF32 mma, gathered A, dual B, SwiGLU*w epilogue ----------------
__global__ __launch_bounds__(256) void moe_up_mma(const float* __restrict__ W1, const float* __restrict__ W3) {
    int e = blockIdx.z, cnt = g_cnt[e], r0 = blockIdx.y * 128;
    if (r0 >= cnt) return;
    int f0 = blockIdx.x * 64;
    __shared__ float As[16][136], B1s[16][72], B3s[16][72];
    __shared__ int toks[128]; __shared__ float wrow[128];
    int tid = threadIdx.x, lane = tid & 31, wid = tid >> 5, grp = lane >> 2, tig = lane & 3;
    int wm = (wid >> 1) * 32, wn = (wid & 1) * 32;
    if (tid < 128) {
        int rr = r0 + tid; bool ok = rr < cnt;
        toks[tid] = ok ? g_tok[e * CT + rr] : g_tok[e * CT];
        wrow[tid] = ok ? g_wsl[e * CT + rr] : 0.f;
    }
    __syncthreads();
    int ar = tid >> 1, akq = (tid & 1) * 8;
    int bk = tid >> 4, bc = (tid & 15) * 4;
    const float* arow = g_hn + (size_t)toks[ar] * CD;
    const float* w1e = W1 + (size_t)e * CD * CF;
    const float* w3e = W3 + (size_t)e * CD * CF;
    float c1[2][4][4] = {}, c3[2][4][4] = {};
    for (int k0 = 0; k0 < CD; k0 += 16) {
        float4 a0 = *(const float4*)&arow[k0 + akq];
        float4 a1 = *(const float4*)&arow[k0 + akq + 4];
        float4 b1 = *(const float4*)&w1e[(size_t)(k0 + bk) * CF + f0 + bc];
        float4 b3 = *(const float4*)&w3e[(size_t)(k0 + bk) * CF + f0 + bc];
        __syncthreads();
        const float* p0 = (const float*)&a0; const float* p1 = (const float*)&a1;
        const float* q1 = (const float*)&b1; const float* q3 = (const float*)&b3;
        #pragma unroll
        for (int j = 0; j < 4; ++j) {
            As[akq + j][ar] = to_tf32(p0[j]);
            As[akq + 4 + j][ar] = to_tf32(p1[j]);
            B1s[bk][bc + j] = to_tf32(q1[j]);
            B3s[bk][bc + j] = to_tf32(q3[j]);
        }
        __syncthreads();
        #pragma unroll
        for (int ks = 0; ks < 16; ks += 8) {
            uint32_t a[2][4];
            #pragma unroll
            for (int i = 0; i < 2; ++i) {
                int r = wm + 16 * i;
                a[i][0] = U32(As[ks + tig][r + grp]);     a[i][1] = U32(As[ks + tig][r + grp + 8]);
                a[i][2] = U32(As[ks + tig + 4][r + grp]); a[i][3] = U32(As[ks + tig + 4][r + grp + 8]);
            }
            #pragma unroll
            for (int j = 0; j < 4; ++j) {
                int cc = wn + 8 * j + grp;
                uint32_t u0 = U32(B1s[ks + tig][cc]), u1 = U32(B1s[ks + tig + 4][cc]);
                uint32_t v0 = U32(B3s[ks + tig][cc]), v1 = U32(B3s[ks + tig + 4][cc]);
                #pragma unroll
                for (int i = 0; i < 2; ++i) { MMA(c1[i][j], a[i], u0, u1); MMA(c3[i][j], a[i], v0, v1); }
            }
        }
    }
    #pragma unroll
    for (int i = 0; i < 2; ++i) {
        int rloc = wm + 16 * i + grp;
        float w0 = wrow[rloc], w1v = wrow[rloc + 8];
        size_t rr0 = (size_t)e * CT + r0 + rloc;
        #pragma unroll
        for (int j = 0; j < 4; ++j) {
            int cc = f0 + wn + 8 * j + 2 * tig;
            float x;
            x = c1[i][j][0]; g_hexp[rr0 * CF + cc]           = (x / (1.f + expf(-x))) * c3[i][j][0] * w0;
            x = c1[i][j][1]; g_hexp[rr0 * CF + cc + 1]       = (x / (1.f + expf(-x))) * c3[i][j][1] * w0;
            x = c1[i][j][2]; g_hexp[(rr0 + 8) * CF + cc]     = (x / (1.f + expf(-x))) * c3[i][j][2] * w1v;
            x = c1[i][j][3]; g_hexp[(rr0 + 8) * CF + cc + 1] = (x / (1.f + expf(-x))) * c3[i][j][3] * w1v;
        }
    }
}

// ---------------- MoE down: 1xTF32 mma ----------------
__global__ __launch_bounds__(256) void moe_down_mma(const float* __restrict__ W2) {
    int e = blockIdx.z, cnt = g_cnt[e], r0 = blockIdx.y * 128;
    if (r0 >= cnt) return;
    int n0 = blockIdx.x * 64;
    const float* A = g_hexp + ((size_t)e * CT + r0) * CF;
    const float* B = W2 + (size_t)e * CF * CD;
    float* C = g_y + ((size_t)e * CT + r0) * CD;
    __shared__ float As[16][136], Bs[16][72];
    int tid = threadIdx.x, lane = tid & 31, wid = tid >> 5, grp = lane >> 2, tig = lane & 3;
    int wm = (wid >> 1) * 32, wn = (wid & 1) * 32;
    int ar = tid >> 1, akq = (tid & 1) * 8;
    int bk = tid >> 4, bc = (tid & 15) * 4;
    float c[2][4][4] = {};
    for (int k0 = 0; k0 < CF; k0 += 16) {
        float4 a0 = *(const float4*)&A[(size_t)ar * CF + k0 + akq];
        float4 a1 = *(const float4*)&A[(size_t)ar * CF + k0 + akq + 4];
        float4 bv = *(const float4*)&B[(size_t)(k0 + bk) * CD + n0 + bc];
        __syncthreads();
        const float* p0 = (const float*)&a0; const float* p1 = (const float*)&a1;
        const float* pb = (const float*)&bv;
        #pragma unroll
        for (int j = 0; j < 4; ++j) {
            As[akq + j][ar] = to_tf32(p0[j]);
            As[akq + 4 + j][ar] = to_tf32(p1[j]);
            Bs[bk][bc + j] = to_tf32(pb[j]);
        }
        __syncthreads();
        #pragma unroll
        for (int ks = 0; ks < 16; ks += 8) {
            uint32_t a[2][4];
            #pragma unroll
            for (int i = 0; i < 2; ++i) {
                int r = wm + 16 * i;
                a[i][0] = U32(As[ks + tig][r + grp]);     a[i][1] = U32(As[ks + tig][r + grp + 8]);
                a[i][2] = U32(As[ks + tig + 4][r + grp]); a[i][3] = U32(As[ks + tig + 4][r + grp + 8]);
            }
            #pragma unroll
            for (int j = 0; j < 4; ++j) {
                int cc = wn + 8 * j + grp;
                uint32_t b0 = U32(Bs[ks + tig][cc]), b1 = U32(Bs[ks + tig + 4][cc]);
                #pragma unroll
                for (int i = 0; i < 2; ++i) MMA(c[i][j], a[i], b0, b1);
            }
        }
    }
    #pragma unroll
    for (int i = 0; i < 2; ++i) {
        int rloc = wm + 16 * i + grp;
        #pragma unroll
        for (int j = 0; j < 4; ++j) {
            int cc = n0 + wn + 8 * j + 2 * tig;
            C[(size_t)rloc * CD + cc]           = c[i][j][0];
            C[(size_t)rloc * CD + cc + 1]       = c[i][j][1];
            C[(size_t)(rloc + 8) * CD + cc]     = c[i][j][2];
            C[(size_t)(rloc + 8) * CD + cc + 1] = c[i][j][3];
        }
    }
}

// ---------------- combine ----------------
__global__ void combine_kernel(float* __restrict__ out) {
    int idx = blockIdx.x * 256 + threadIdx.x;
    if (idx >= CT * CD) return;
    int t = idx >> 10, d = idx & 1023;
    int s0 = g_slot[t * 2 + 0], s1 = g_slot[t * 2 + 1];
    out[idx] = g_h1[idx] + g_y[(size_t)s0 * CD + d] + g_y[(size_t)s1 * CD + d];
}

// ---------------- launcher ----------------
extern "C" void kernel_launch(void* const* d_in, const int* in_sizes, int n_in,
                              void* d_out, int out_size) {
    const float* hid = (const float*)d_in[0];
    const int*   pos = (const int*)  d_in[1];
    const float* ln1 = (const float*)d_in[3];
    const float* ln2 = (const float*)d_in[4];
    const float* wq  = (const float*)d_in[5];
    const float* wk  = (const float*)d_in[6];
    const float* wv  = (const float*)d_in[7];
    const float* wo  = (const float*)d_in[8];
    const float* gw  = (const float*)d_in[9];
    const float* w1  = (const float*)d_in[10];
    const float* w3  = (const float*)d_in[11];
    const float* w2  = (const float*)d_in[12];
    float* out        = (float*)d_out;
    float* out_scores = out + (size_t)CT * CD;

    float* xn;  cudaGetSymbolAddress((void**)&xn,  g_xn);
    float* q;   cudaGetSymbolAddress((void**)&q,   g_q);
    float* k;   cudaGetSymbolAddress((void**)&k,   g_k);
    float* v;   cudaGetSymbolAddress((void**)&v,   g_v);
    float* att; cudaGetSymbolAddress((void**)&att, g_att);
    float* h1;  cudaGetSymbolAddress((void**)&h1,  g_h1);
    float* hn;  cudaGetSymbolAddress((void**)&hn,  g_hn);
    int*   cnt; cudaGetSymbolAddress((void**)&cnt, g_cnt);

    cudaFuncSetAttribute(flash_kernel, cudaFuncAttributeMaxDynamicSharedMemorySize, FLASH_SMEM);

    rmsnorm_kernel<<<CT, 256>>>(hid, ln1, xn);
    mma_gemm<true><<<dim3(16, 16), 256>>>(xn, wq, nullptr, q, CT, CH * CHD, CD);
    mma_gemm<true><<<dim3(4, 16),  256>>>(xn, wk, nullptr, k, CT, CKV * CHD, CD);
    mma_gemm<true><<<dim3(4, 16),  256>>>(xn, wv, nullptr, v, CT, CKV * CHD, CD);
    {
        int total = CT * (CH + CKV) * 32;
        rope_kernel<<<(total + 255) / 256, 256>>>(pos);
    }
    flash_kernel<<<dim3(CB * CH, CS / 64), 256, FLASH_SMEM>>>();
    mma_gemm<true><<<dim3(16, 16), 256>>>(att, wo, hid, h1, CT, CD, CH * CHD);
    rmsnorm_kernel<<<CT, 256>>>(h1, ln2, hn);
    cudaMemsetAsync(cnt, 0, CE * sizeof(int));
    router_kernel<<<(CT * 32 + 255) / 256, 256>>>(gw, out_scores);
    moe_up_mma<<<dim3(CF / 64, CT / 128, CE), 256>>>(w1, w3);
    moe_down_mma<<<dim3(CD / 64, CT / 128, CE), 256>>>(w2);
    combine_kernel<<<(CT * CD + 255) / 256, 256>>>(out);
}

// round 4
// speedup vs baseline: 2.9498x; 1.4284x over previous
#include <cuda_runtime.h>
#include <math.h>
#include <stdint.h>

constexpr int CB = 2, CS = 1024, CD = 1024;
constexpr int CH = 16, CKV = 4, CHD = 64;
constexpr int CE = 8, CF = 2048;
constexpr int CT = CB * CS;
constexpr float CEPS = 1e-6f;

__device__ float g_xn [CT * CD];
__device__ float g_q  [CT * CH  * CHD];
__device__ float g_k  [CT * CKV * CHD];
__device__ float g_v  [CT * CKV * CHD];
__device__ float g_att[CT * CH  * CHD];
__device__ float g_h1 [CT * CD];
__device__ float g_hn [CT * CD];
__device__ int   g_cnt [CE];
__device__ int   g_tok [CE * CT];
__device__ float g_wsl [CE * CT];
__device__ int   g_slot[CT * 2];
__device__ float g_hexp[(size_t)CE * CT * CF];
__device__ float g_y   [(size_t)CE * CT * CD];

__device__ __forceinline__ float to_tf32(float x) {
    float r; asm("cvt.rna.tf32.f32 %0, %1;" : "=f"(r) : "f"(x)); return r;
}
#define U32(x) __float_as_uint(x)
#define MMA(c, a, b0, b1) \
    asm volatile("mma.sync.aligned.m16n8k8.row.col.f32.tf32.tf32.f32 " \
        "{%0,%1,%2,%3}, {%4,%5,%6,%7}, {%8,%9}, {%0,%1,%2,%3};" \
        : "+f"((c)[0]), "+f"((c)[1]), "+f"((c)[2]), "+f"((c)[3]) \
        : "r"((a)[0]), "r"((a)[1]), "r"((a)[2]), "r"((a)[3]), "r"(b0), "r"(b1))

__device__ __forceinline__ void cpa16(uint32_t d, const float* s) {
    asm volatile("cp.async.ca.shared.global [%0], [%1], 16;" :: "r"(d), "l"(s));
}
#define CPC  asm volatile("cp.async.commit_group;")
#define CPW(n) asm volatile("cp.async.wait_group %0;" :: "n"(n))

// ------------- shared double-buffered MMA core: 128x64xK, 256 thr -------------
// smem: smA 2 stages [128][20] raw fp32; smB1/smB3 2 stages [16][72] raw fp32.
constexpr int ASTG = 128 * 20;   // floats per A stage
constexpr int BSTG = 16 * 72;

template<bool TRIPLE, bool DUAL>
__device__ __forceinline__ void mma_core(
    const float* pA0, const float* pA1,          // this thread's 2 A-row base ptrs (k=0)
    const float* pB1, const float* pB3,          // this thread's B chunk ptrs (at its kB,nB)
    int ldb, int K,
    float* smA, float* smB1, float* smB3, int tid,
    float c1[2][4][4], float c3[2][4][4])
{
    const int kcA = (tid & 3) * 4;
    const int lane = tid & 31, wid = tid >> 5, grp = lane >> 2, tig = lane & 3;
    const int wm = (wid >> 1) * 32, wn = (wid & 1) * 32;
    uint32_t sA0 = (uint32_t)__cvta_generic_to_shared(smA) + (((tid >> 2) * 20 + kcA) << 2);
    uint32_t sA1 = sA0 + (64 * 20 << 2);
    uint32_t sB1 = (uint32_t)__cvta_generic_to_shared(smB1) + ((((tid >> 4) * 72) + (tid & 15) * 4) << 2);
    uint32_t sB3 = DUAL ? (uint32_t)__cvta_generic_to_shared(smB3) + ((((tid >> 4) * 72) + (tid & 15) * 4) << 2) : 0u;

    // prologue: tile 0 -> stage 0
    cpa16(sA0, pA0 + kcA);
    cpa16(sA1, pA1 + kcA);
    cpa16(sB1, pB1);
    if (DUAL) cpa16(sB3, pB3);
    CPC;

    int nt = K / 16;
    for (int t = 0; t < nt; ++t) {
        if (t + 1 < nt) {
            int k0 = (t + 1) * 16, st = (t + 1) & 1;
            cpa16(sA0 + st * (ASTG << 2), pA0 + k0 + kcA);
            cpa16(sA1 + st * (ASTG << 2), pA1 + k0 + kcA);
            cpa16(sB1 + st * (BSTG << 2), pB1 + (size_t)k0 * ldb);
            if (DUAL) cpa16(sB3 + st * (BSTG << 2), pB3 + (size_t)k0 * ldb);
            CPC; CPW(1);
        } else { CPW(0); }
        __syncthreads();
        const float* As = smA  + (t & 1) * ASTG;
        const float* B1 = smB1 + (t & 1) * BSTG;
        const float* B3 = smB3 + (t & 1) * BSTG;
        #pragma unroll
        for (int ks = 0; ks < 16; ks += 8) {
            uint32_t ah[2][4], al[2][4];
            #pragma unroll
            for (int i = 0; i < 2; ++i)
                #pragma unroll
                for (int u = 0; u < 4; ++u) {
                    int kk = ks + tig + (u >> 1) * 4;
                    int rr = wm + 16 * i + grp + (u & 1) * 8;
                    float x = As[rr * 20 + kk];
                    float h = to_tf32(x);
                    ah[i][u] = U32(h);
                    if (TRIPLE) al[i][u] = U32(to_tf32(x - h));
                }
            #pragma unroll
            for (int j = 0; j < 4; ++j) {
                int cc = wn + 8 * j + grp;
                float x0 = B1[(ks + tig) * 72 + cc], x1 = B1[(ks + tig + 4) * 72 + cc];
                if (TRIPLE) {
                    float h0 = to_tf32(x0), h1 = to_tf32(x1);
                    uint32_t bh0 = U32(h0), bh1 = U32(h1);
                    uint32_t bl0 = U32(to_tf32(x0 - h0)), bl1 = U32(to_tf32(x1 - h1));
                    #pragma unroll
                    for (int i = 0; i < 2; ++i) {
                        MMA(c1[i][j], ah[i], bh0, bh1);
                        MMA(c1[i][j], ah[i], bl0, bl1);
                        MMA(c1[i][j], al[i], bh0, bh1);
                    }
                } else {
                    uint32_t bh0 = U32(to_tf32(x0)), bh1 = U32(to_tf32(x1));
                    #pragma unroll
                    for (int i = 0; i < 2; ++i) MMA(c1[i][j], ah[i], bh0, bh1);
                    if (DUAL) {
                        float y0 = B3[(ks + tig) * 72 + cc], y1 = B3[(ks + tig + 4) * 72 + cc];
                        uint32_t d0 = U32(to_tf32(y0)), d1 = U32(to_tf32(y1));
                        #pragma unroll
                        for (int i = 0; i < 2; ++i) MMA(c3[i][j], ah[i], d0, d1);
                    }
                }
            }
        }
        __syncthreads();
    }
}

// ---------------- RMSNorm ----------------
__global__ void rmsnorm_kernel(const float* __restrict__ x, const float* __restrict__ w,
                               float* __restrict__ out) {
    int t = blockIdx.x;
    const float* xr = x + (size_t)t * CD;
    float ss = 0.f;
    for (int d = threadIdx.x; d < CD; d += 256) { float v = xr[d]; ss += v * v; }
    __shared__ float red[256];
    red[threadIdx.x] = ss;
    __syncthreads();
    for (int s = 128; s > 0; s >>= 1) {
        if (threadIdx.x < s) red[threadIdx.x] += red[threadIdx.x + s];
        __syncthreads();
    }
    __shared__ float rinv;
    if (threadIdx.x == 0) rinv = rsqrtf(red[0] * (1.f / CD) + CEPS);
    __syncthreads();
    float* orow = out + (size_t)t * CD;
    for (int d = threadIdx.x; d < CD; d += 256) orow[d] = xr[d] * rinv * w[d];
}

// ---------------- fused QKV projection (3xTF32) ----------------
__global__ __launch_bounds__(256, 2) void qkv_kernel(
    const float* __restrict__ wq, const float* __restrict__ wk, const float* __restrict__ wv)
{
    __shared__ __align__(16) float smA[2 * ASTG];
    __shared__ __align__(16) float smB[2 * BSTG];
    int n0 = blockIdx.x * 64, m0 = blockIdx.y * 128, tid = threadIdx.x;
    const float* B; float* C; int ldb, nc;
    if (n0 < 1024)      { B = wq; C = g_q; ldb = 1024; nc = n0; }
    else if (n0 < 1280) { B = wk; C = g_k; ldb = 256;  nc = n0 - 1024; }
    else                { B = wv; C = g_v; ldb = 256;  nc = n0 - 1280; }
    const float* pA0 = g_xn + (size_t)(m0 + (tid >> 2)) * CD;
    const float* pA1 = pA0 + (size_t)64 * CD;
    const float* pB  = B + (size_t)(tid >> 4) * ldb + nc + (tid & 15) * 4;
    float c1[2][4][4] = {};
    mma_core<true, false>(pA0, pA1, pB, pB, ldb, CD, smA, smB, smB, tid, c1, c1);
    int lane = tid & 31, wid = tid >> 5, grp = lane >> 2, tig = lane & 3;
    int wm = (wid >> 1) * 32, wn = (wid & 1) * 32;
    #pragma unroll
    for (int i = 0; i < 2; ++i) {
        int r = m0 + wm + 16 * i + grp;
        #pragma unroll
        for (int j = 0; j < 4; ++j) {
            int cc = nc + wn + 8 * j + 2 * tig;
            *(float2*)&C[(size_t)r * ldb + cc]       = make_float2(c1[i][j][0], c1[i][j][1]);
            *(float2*)&C[(size_t)(r + 8) * ldb + cc] = make_float2(c1[i][j][2], c1[i][j][3]);
        }
    }
}

// ---------------- O projection + residual (3xTF32) ----------------
__global__ __launch_bounds__(256, 2) void oproj_kernel(
    const float* __restrict__ wo, const float* __restrict__ Res)
{
    __shared__ __align__(16) float smA[2 * ASTG];
    __shared__ __align__(16) float smB[2 * BSTG];
    int n0 = blockIdx.x * 64, m0 = blockIdx.y * 128, tid = threadIdx.x;
    const float* pA0 = g_att + (size_t)(m0 + (tid >> 2)) * CD;
    const float* pA1 = pA0 + (size_t)64 * CD;
    const float* pB  = wo + (size_t)(tid >> 4) * CD + n0 + (tid & 15) * 4;
    float c1[2][4][4] = {};
    mma_core<true, false>(pA0, pA1, pB, pB, CD, CD, smA, smB, smB, tid, c1, c1);
    int lane = tid & 31, wid = tid >> 5, grp = lane >> 2, tig = lane & 3;
    int wm = (wid >> 1) * 32, wn = (wid & 1) * 32;
    #pragma unroll
    for (int i = 0; i < 2; ++i) {
        int r = m0 + wm + 16 * i + grp;
        #pragma unroll
        for (int j = 0; j < 4; ++j) {
            int cc = n0 + wn + 8 * j + 2 * tig;
            size_t i0 = (size_t)r * CD + cc, i1 = (size_t)(r + 8) * CD + cc;
            float2 r0 = *(const float2*)&Res[i0], r1 = *(const float2*)&Res[i1];
            *(float2*)&g_h1[i0] = make_float2(c1[i][j][0] + r0.x, c1[i][j][1] + r0.y);
            *(float2*)&g_h1[i1] = make_float2(c1[i][j][2] + r1.x, c1[i][j][3] + r1.y);
        }
    }
}

// ---------------- RoPE ----------------
__global__ void rope_kernel(const int* __restrict__ pos_ids) {
    int idx = blockIdx.x * 256 + threadIdx.x;
    const int nq = CT * CH * 32, nk = CT * CKV * 32;
    if (idx >= nq + nk) return;
    float* base; int i, t;
    if (idx < nq) {
        i = idx & 31; int th = idx >> 5; int h = th % CH; t = th / CH;
        base = g_q + ((size_t)t * CH + h) * CHD;
    } else {
        int id2 = idx - nq;
        i = id2 & 31; int th = id2 >> 5; int h = th % CKV; t = th / CKV;
        base = g_k + ((size_t)t * CKV + h) * CHD;
    }
    float p = (float)pos_ids[t];
    float freq = expf(-(2.f * i / (float)CHD) * logf(10000.f));
    float ang = p * freq, c = cosf(ang), s = sinf(ang);
    float x0 = base[i], x1 = base[i + 32];
    base[i] = x0 * c - x1 * s;
    base[i + 32] = x1 * c + x0 * s;
}

// ---------------- flash attention, 3xTF32 mma ----------------
// 128 threads; smem: Q(->P) [64][72], K [64][72], V [64][72] raw fp32
constexpr int FL_SMEM = 3 * 64 * 72 * 4;
__global__ __launch_bounds__(128) void flash_mma() {
    extern __shared__ float fs[];
    float* Qs = fs;                 // reused as P after Q frags move to regs
    float* Ks = fs + 64 * 72;
    float* Vs = fs + 2 * 64 * 72;
    int bh = blockIdx.x, qt = blockIdx.y;
    int b = bh >> 4, h = bh & 15, kvh = h >> 2;
    int tid = threadIdx.x, lane = tid & 31, warp = tid >> 5, grp = lane >> 2, tig = lane & 3;
    int rl0 = warp * 16 + grp;

    #pragma unroll
    for (int it = 0; it < 8; ++it) {
        int idx = tid + it * 128;
        int r = idx >> 4, d4 = (idx & 15) * 4;
        float4 qv = *(const float4*)&g_q[((size_t)(b * CS + qt * 64 + r) * CH + h) * CHD + d4];
        Qs[r * 72 + d4]     = qv.x * 0.125f;
        Qs[r * 72 + d4 + 1] = qv.y * 0.125f;
        Qs[r * 72 + d4 + 2] = qv.z * 0.125f;
        Qs[r * 72 + d4 + 3] = qv.w * 0.125f;
    }
    __syncthreads();

    uint32_t qh[8][4], ql[8][4];
    #pragma unroll
    for (int ks = 0; ks < 8; ++ks)
        #pragma unroll
        for (int u = 0; u < 4; ++u) {
            int kk = ks * 8 + tig + (u >> 1) * 4;
            int rr = warp * 16 + grp + (u & 1) * 8;
            float x = Qs[rr * 72 + kk];
            float hv = to_tf32(x);
            qh[ks][u] = U32(hv);
            ql[ks][u] = U32(to_tf32(x - hv));
        }

    float o[8][4] = {};
    float m0v = -INFINITY, m1v = -INFINITY, l0v = 0.f, l1v = 0.f;

    for (int kt = 0; kt <= qt; ++kt) {
        __syncthreads();   // previous iter done reading Ks/Vs (and Q frags done, iter 0)
        #pragma unroll
        for (int it = 0; it < 8; ++it) {
            int idx = tid + it * 128;
            int n = idx >> 4, d4 = (idx & 15) * 4;
            size_t gb = ((size_t)(b * CS + kt * 64 + n) * CKV + kvh) * CHD + d4;
            *(float4*)&Ks[n * 72 + d4] = *(const float4*)&g_k[gb];
            *(float4*)&Vs[n * 72 + d4] = *(const float4*)&g_v[gb];
        }
        __syncthreads();

        // S = Q K^T
        float s[8][4] = {};
        #pragma unroll
        for (int ks = 0; ks < 8; ++ks)
            #pragma unroll
            for (int j = 0; j < 8; ++j) {
                float x0 = Ks[(8 * j + grp) * 72 + ks * 8 + tig];
                float x1 = Ks[(8 * j + grp) * 72 + ks * 8 + tig + 4];
                float h0 = to_tf32(x0), h1 = to_tf32(x1);
                uint32_t bh0 = U32(h0), bh1 = U32(h1);
                uint32_t bl0 = U32(to_tf32(x0 - h0)), bl1 = U32(to_tf32(x1 - h1));
                MMA(s[j], qh[ks], bh0, bh1);
                MMA(s[j], qh[ks], bl0, bl1);
                MMA(s[j], ql[ks], bh0, bh1);
            }
        if (kt == qt) {
            #pragma unroll
            for (int j = 0; j < 8; ++j) {
                int cg = 8 * j + 2 * tig;
                if (cg     > rl0)     s[j][0] = -INFINITY;
                if (cg + 1 > rl0)     s[j][1] = -INFINITY;
                if (cg     > rl0 + 8) s[j][2] = -INFINITY;
                if (cg + 1 > rl0 + 8) s[j][3] = -INFINITY;
            }
        }
        float mx0 = -INFINITY, mx1 = -INFINITY;
        #pragma unroll
        for (int j = 0; j < 8; ++j) {
            mx0 = fmaxf(mx0, fmaxf(s[j][0], s[j][1]));
            mx1 = fmaxf(mx1, fmaxf(s[j][2], s[j][3]));
        }
        mx0 = fmaxf(mx0, __shfl_xor_sync(0xffffffffu, mx0, 1));
        mx0 = fmaxf(mx0, __shfl_xor_sync(0xffffffffu, mx0, 2));
        mx1 = fmaxf(mx1, __shfl_xor_sync(0xffffffffu, mx1, 1));
        mx1 = fmaxf(mx1, __shfl_xor_sync(0xffffffffu, mx1, 2));
        float mn0 = fmaxf(m0v, mx0), mn1 = fmaxf(m1v, mx1);
        float al0 = expf(m0v - mn0), al1 = expf(m1v - mn1);
        float s0 = 0.f, s1 = 0.f;
        #pragma unroll
        for (int j = 0; j < 8; ++j) {
            s[j][0] = expf(s[j][0] - mn0); s[j][1] = expf(s[j][1] - mn0);
            s[j][2] = expf(s[j][2] - mn1); s[j][3] = expf(s[j][3] - mn1);
            s0 += s[j][0] + s[j][1];
            s1 += s[j][2] + s[j][3];
        }
        s0 += __shfl_xor_sync(0xffffffffu, s0, 1); s0 += __shfl_xor_sync(0xffffffffu, s0, 2);
        s1 += __shfl_xor_sync(0xffffffffu, s1, 1); s1 += __shfl_xor_sync(0xffffffffu, s1, 2);
        l0v = l0v * al0 + s0; l1v = l1v * al1 + s1;
        m0v = mn0; m1v = mn1;
        #pragma unroll
        for (int j = 0; j < 8; ++j) {
            o[j][0] *= al0; o[j][1] *= al0; o[j][2] *= al1; o[j][3] *= al1;
        }
        // P -> smem (warp-private rows of Qs)
        #pragma unroll
        for (int j = 0; j < 8; ++j) {
            int cc = 8 * j + 2 * tig;
            Qs[rl0 * 72 + cc]           = s[j][0];
            Qs[rl0 * 72 + cc + 1]       = s[j][1];
            Qs[(rl0 + 8) * 72 + cc]     = s[j][2];
            Qs[(rl0 + 8) * 72 + cc + 1] = s[j][3];
        }
        __syncwarp();
        // O += P V
        #pragma unroll
        for (int ks = 0; ks < 8; ++ks) {
            uint32_t ph[4], pl[4];
            #pragma unroll
            for (int u = 0; u < 4; ++u) {
                int kk = ks * 8 + tig + (u >> 1) * 4;
                int rr = warp * 16 + grp + (u & 1) * 8;
                float x = Qs[rr * 72 + kk];
                float hv = to_tf32(x);
                ph[u] = U32(hv);
                pl[u] = U32(to_tf32(x - hv));
            }
            #pragma unroll
            for (int j = 0; j < 8; ++j) {
                float x0 = Vs[(ks * 8 + tig) * 72 + 8 * j + grp];
                float x1 = Vs[(ks * 8 + tig + 4) * 72 + 8 * j + grp];
                float h0 = to_tf32(x0), h1 = to_tf32(x1);
                uint32_t vh0 = U32(h0), vh1 = U32(h1);
                uint32_t vl0 = U32(to_tf32(x0 - h0)), vl1 = U32(to_tf32(x1 - h1));
                MMA(o[j], ph, vh0, vh1);
                MMA(o[j], ph, vl0, vl1);
                MMA(o[j], pl, vh0, vh1);
            }
        }
    }

    float i0 = 1.f / l0v, i1 = 1.f / l1v;
    size_t t0 = (size_t)(b * CS + qt * 64 + rl0);
    #pragma unroll
    for (int j = 0; j < 8; ++j) {
        int d = 8 * j + 2 * tig;
        *(float2*)&g_att[(t0 * CH + h) * CHD + d]       = make_float2(o[j][0] * i0, o[j][1] * i0);
        *(float2*)&g_att[((t0 + 8) * CH + h) * CHD + d] = make_float2(o[j][2] * i1, o[j][3] * i1);
    }
}

// ---------------- router ----------------
__global__ void router_kernel(const float* __restrict__ Gw, float* __restrict__ scores_out) {
    int gtid = blockIdx.x * blockDim.x + threadIdx.x;
    int warp = gtid >> 5, lane = threadIdx.x & 31;
    if (warp >= CT) return;
    const float* xr = g_hn + (size_t)warp * CD;
    float acc[CE] = {};
    for (int d = lane; d < CD; d += 32) {
        float xv = xr[d];
        const float* gr = Gw + (size_t)d * CE;
        #pragma unroll
        for (int e = 0; e < CE; ++e) acc[e] += xv * gr[e];
    }
    #pragma unroll
    for (int off = 16; off; off >>= 1)
        #pragma unroll
        for (int e = 0; e < CE; ++e) acc[e] += __shfl_down_sync(0xffffffffu, acc[e], off);
    if (lane == 0) {
        float mx = acc[0];
        #pragma unroll
        for (int e = 1; e < CE; ++e) mx = fmaxf(mx, acc[e]);
        float p[CE], sum = 0.f;
        #pragma unroll
        for (int e = 0; e < CE; ++e) { p[e] = expf(acc[e] - mx); sum += p[e]; }
        float inv = 1.f / sum;
        #pragma unroll
        for (int e = 0; e < CE; ++e) { p[e] *= inv; scores_out[(size_t)warp * CE + e] = p[e]; }
        int e0 = 0; float b0 = p[0];
        #pragma unroll
        for (int e = 1; e < CE; ++e) if (p[e] > b0) { b0 = p[e]; e0 = e; }
        int e1 = -1; float b1 = -1.f;
        #pragma unroll
        for (int e = 0; e < CE; ++e) if (e != e0 && p[e] > b1) { b1 = p[e]; e1 = e; }
        float wsum = b0 + b1;
        int p0 = atomicAdd(&g_cnt[e0], 1);
        g_tok[e0 * CT + p0] = warp; g_wsl[e0 * CT + p0] = b0 / wsum;
        g_slot[warp * 2 + 0] = e0 * CT + p0;
        int p1 = atomicAdd(&g_cnt[e1], 1);
        g_tok[e1 * CT + p1] = warp; g_wsl[e1 * CT + p1] = b1 / wsum;
        g_slot[warp * 2 + 1] = e1 * CT + p1;
    }
}

// ---------------- MoE up (1xTF32, dual B, gathered A, SwiGLU*w epilogue) ----------------
__global__ __launch_bounds__(256, 2) void moe_up_mma(
    const float* __restrict__ W1, const float* __restrict__ W3)
{
    int e = blockIdx.z, cnt = g_cnt[e], r0 = blockIdx.y * 128;
    if (r0 >= cnt) return;
    int f0 = blockIdx.x * 64, tid = threadIdx.x;
    __shared__ __align__(16) float smA[2 * ASTG];
    __shared__ __align__(16) float smB1[2 * BSTG];
    __shared__ __align__(16) float smB3[2 * BSTG];
    __shared__ int toks[128]; __shared__ float wrow[128];
    if (tid < 128) {
        int rr = r0 + tid; bool ok = rr < cnt;
        toks[tid] = ok ? g_tok[e * CT + rr] : g_tok[e * CT];
        wrow[tid] = ok ? g_wsl[e * CT + rr] : 0.f;
    }
    __syncthreads();
    const float* pA0 = g_hn + (size_t)toks[tid >> 2] * CD;
    const float* pA1 = g_hn + (size_t)toks[(tid >> 2) + 64] * CD;
    const float* w1e = W1 + (size_t)e * CD * CF;
    const float* w3e = W3 + (size_t)e * CD * CF;
    const float* pB1 = w1e + (size_t)(tid >> 4) * CF + f0 + (tid & 15) * 4;
    const float* pB3 = w3e + (size_t)(tid >> 4) * CF + f0 + (tid & 15) * 4;
    float c1[2][4][4] = {}, c3[2][4][4] = {};
    mma_core<false, true>(pA0, pA1, pB1, pB3, CF, CD, smA, smB1, smB3, tid, c1, c3);
    int lane = tid & 31, wid = tid >> 5, grp = lane >> 2, tig = lane & 3;
    int wm = (wid >> 1) * 32, wn = (wid & 1) * 32;
    #pragma unroll
    for (int i = 0; i < 2; ++i) {
        int rloc = wm + 16 * i + grp;
        float w0 = wrow[rloc], w1v = wrow[rloc + 8];
        size_t rr0 = (size_t)e * CT + r0 + rloc;
        #pragma unroll
        for (int j = 0; j < 4; ++j) {
            int cc = f0 + wn + 8 * j + 2 * tig;
            float x0 = c1[i][j][0], x1 = c1[i][j][1], x2 = c1[i][j][2], x3 = c1[i][j][3];
            *(float2*)&g_hexp[rr0 * CF + cc] = make_float2(
                (x0 / (1.f + expf(-x0))) * c3[i][j][0] * w0,
                (x1 / (1.f + expf(-x1))) * c3[i][j][1] * w0);
            *(float2*)&g_hexp[(rr0 + 8) * CF + cc] = make_float2(
                (x2 / (1.f + expf(-x2))) * c3[i][j][2] * w1v,
                (x3 / (1.f + expf(-x3))) * c3[i][j][3] * w1v);
        }
    }
}

// ---------------- MoE down (1xTF32) ----------------
__global__ __launch_bounds__(256, 2) void moe_down_mma(const float* __restrict__ W2) {
    int e = blockIdx.z, cnt = g_cnt[e], r0 = blockIdx.y * 128;
    if (r0 >= cnt) return;
    int n0 = blockIdx.x * 64, tid = threadIdx.x;
    __shared__ __align__(16) float smA[2 * ASTG];
    __shared__ __align__(16) float smB[2 * BSTG];
    const float* A = g_hexp + ((size_t)e * CT + r0) * CF;
    const float* B = W2 + (size_t)e * CF * CD;
    const float* pA0 = A + (size_t)(tid >> 2) * CF;
    const float* pA1 = pA0 + (size_t)64 * CF;
    const float* pB  = B + (size_t)(tid >> 4) * CD + n0 + (tid & 15) * 4;
    float c1[2][4][4] = {};
    mma_core<false, false>(pA0, pA1, pB, pB, CD, CF, smA, smB, smB, tid, c1, c1);
    float* C = g_y + ((size_t)e * CT + r0) * CD;
    int lane = tid & 31, wid = tid >> 5, grp = lane >> 2, tig = lane & 3;
    int wm = (wid >> 1) * 32, wn = (wid & 1) * 32;
    #pragma unroll
    for (int i = 0; i < 2; ++i) {
        int rloc = wm + 16 * i + grp;
        #pragma unroll
        for (int j = 0; j < 4; ++j) {
            int cc = n0 + wn + 8 * j + 2 * tig;
            *(float2*)&C[(size_t)rloc * CD + cc]       = make_float2(c1[i][j][0], c1[i][j][1]);
            *(float2*)&C[(size_t)(rloc + 8) * CD + cc] = make_float2(c1[i][j][2], c1[i][j][3]);
        }
    }
}

// ---------------- combine ----------------
__global__ void combine_kernel(float* __restrict__ out) {
    int idx = blockIdx.x * 256 + threadIdx.x;
    if (idx >= CT * CD) return;
    int t = idx >> 10, d = idx & 1023;
    int s0 = g_slot[t * 2 + 0], s1 = g_slot[t * 2 + 1];
    out[idx] = g_h1[idx] + g_y[(size_t)s0 * CD + d] + g_y[(size_t)s1 * CD + d];
}

// ---------------- launcher ----------------
extern "C" void kernel_launch(void* const* d_in, const int* in_sizes, int n_in,
                              void* d_out, int out_size) {
    const float* hid = (const float*)d_in[0];
    const int*   pos = (const int*)  d_in[1];
    const float* ln1 = (const float*)d_in[3];
    const float* ln2 = (const float*)d_in[4];
    const float* wq  = (const float*)d_in[5];
    const float* wk  = (const float*)d_in[6];
    const float* wv  = (const float*)d_in[7];
    const float* wo  = (const float*)d_in[8];
    const float* gw  = (const float*)d_in[9];
    const float* w1  = (const float*)d_in[10];
    const float* w3  = (const float*)d_in[11];
    const float* w2  = (const float*)d_in[12];
    float* out        = (float*)d_out;
    float* out_scores = out + (size_t)CT * CD;

    float* xn;  cudaGetSymbolAddress((void**)&xn,  g_xn);
    float* h1;  cudaGetSymbolAddress((void**)&h1,  g_h1);
    float* hn;  cudaGetSymbolAddress((void**)&hn,  g_hn);
    int*   cnt; cudaGetSymbolAddress((void**)&cnt, g_cnt);

    cudaFuncSetAttribute(flash_mma, cudaFuncAttributeMaxDynamicSharedMemorySize, FL_SMEM);

    rmsnorm_kernel<<<CT, 256>>>(hid, ln1, xn);
    qkv_kernel<<<dim3(24, 16), 256>>>(wq, wk, wv);
    {
        int total = CT * (CH + CKV) * 32;
        rope_kernel<<<(total + 255) / 256, 256>>>(pos);
    }
    flash_mma<<<dim3(CB * CH, CS / 64), 128, FL_SMEM>>>();
    oproj_kernel<<<dim3(16, 16), 256>>>(wo, hid);
    rmsnorm_kernel<<<CT, 256>>>(h1, ln2, hn);
    cudaMemsetAsync(cnt, 0, CE * sizeof(int));
    router_kernel<<<(CT * 32 + 255) / 256, 256>>>(gw, out_scores);
    moe_up_mma<<<dim3(CF / 64, CT / 128, CE), 256>>>(w1, w3);
    moe_down_mma<<<dim3(CD / 64, CT / 128, CE), 256>>>(w2);
    combine_kernel<<<(CT * CD + 255) / 256, 256>>>(out);
}

// round 5
// speedup vs baseline: 3.2124x; 1.0890x over previous
#include <cuda_runtime.h>
#include <math.h>
#include <stdint.h>

constexpr int CB = 2, CS = 1024, CD = 1024;
constexpr int CH = 16, CKV = 4, CHD = 64;
constexpr int CE = 8, CF = 2048;
constexpr int CT = CB * CS;
constexpr float CEPS = 1e-6f;

__device__ float g_xn [CT * CD];
__device__ float g_q  [CT * CH  * CHD];
__device__ float g_k  [CT * CKV * CHD];
__device__ float g_v  [CT * CKV * CHD];
__device__ float g_att[CT * CH  * CHD];
__device__ float g_h1 [CT * CD];
__device__ float g_hn [CT * CD];
__device__ int   g_cnt [CE];
__device__ int   g_tok [CE * CT];
__device__ float g_wsl [CE * CT];
__device__ int   g_slot[CT * 2];
__device__ float g_hexp[(size_t)CE * CT * CF];
__device__ float g_y   [(size_t)CE * CT * CD];

__device__ __forceinline__ float to_tf32(float x) {
    float r; asm("cvt.rna.tf32.f32 %0, %1;" : "=f"(r) : "f"(x)); return r;
}
#define U32(x) __float_as_uint(x)
#define MMA(c, a, b0, b1) \
    asm volatile("mma.sync.aligned.m16n8k8.row.col.f32.tf32.tf32.f32 " \
        "{%0,%1,%2,%3}, {%4,%5,%6,%7}, {%8,%9}, {%0,%1,%2,%3};" \
        : "+f"((c)[0]), "+f"((c)[1]), "+f"((c)[2]), "+f"((c)[3]) \
        : "r"((a)[0]), "r"((a)[1]), "r"((a)[2]), "r"((a)[3]), "r"(b0), "r"(b1))

__device__ __forceinline__ void cpa16(uint32_t d, const float* s) {
    asm volatile("cp.async.ca.shared.global [%0], [%1], 16;" :: "r"(d), "l"(s));
}
#define CPC  asm volatile("cp.async.commit_group;")
#define CPW(n) asm volatile("cp.async.wait_group %0;" :: "n"(n))

// ------------- shared double-buffered MMA core: 128x64xK, 256 thr -------------
constexpr int ASTG = 128 * 20;
constexpr int BSTG = 16 * 72;

template<bool TRIPLE, bool DUAL>
__device__ __forceinline__ void mma_core(
    const float* pA0, const float* pA1,
    const float* pB1, const float* pB3,
    int ldb, int K,
    float* smA, float* smB1, float* smB3, int tid,
    float c1[2][4][4], float c3[2][4][4])
{
    const int kcA = (tid & 3) * 4;
    const int lane = tid & 31, wid = tid >> 5, grp = lane >> 2, tig = lane & 3;
    const int wm = (wid >> 1) * 32, wn = (wid & 1) * 32;
    uint32_t sA0 = (uint32_t)__cvta_generic_to_shared(smA) + (((tid >> 2) * 20 + kcA) << 2);
    uint32_t sA1 = sA0 + (64 * 20 << 2);
    uint32_t sB1 = (uint32_t)__cvta_generic_to_shared(smB1) + ((((tid >> 4) * 72) + (tid & 15) * 4) << 2);
    uint32_t sB3 = DUAL ? (uint32_t)__cvta_generic_to_shared(smB3) + ((((tid >> 4) * 72) + (tid & 15) * 4) << 2) : 0u;

    cpa16(sA0, pA0 + kcA);
    cpa16(sA1, pA1 + kcA);
    cpa16(sB1, pB1);
    if (DUAL) cpa16(sB3, pB3);
    CPC;

    int nt = K / 16;
    for (int t = 0; t < nt; ++t) {
        if (t + 1 < nt) {
            int k0 = (t + 1) * 16, st = (t + 1) & 1;
            cpa16(sA0 + st * (ASTG << 2), pA0 + k0 + kcA);
            cpa16(sA1 + st * (ASTG << 2), pA1 + k0 + kcA);
            cpa16(sB1 + st * (BSTG << 2), pB1 + (size_t)k0 * ldb);
            if (DUAL) cpa16(sB3 + st * (BSTG << 2), pB3 + (size_t)k0 * ldb);
            CPC; CPW(1);
        } else { CPW(0); }
        __syncthreads();
        const float* As = smA  + (t & 1) * ASTG;
        const float* B1 = smB1 + (t & 1) * BSTG;
        const float* B3 = smB3 + (t & 1) * BSTG;
        #pragma unroll
        for (int ks = 0; ks < 16; ks += 8) {
            uint32_t ah[2][4], al[2][4];
            #pragma unroll
            for (int i = 0; i < 2; ++i)
                #pragma unroll
                for (int u = 0; u < 4; ++u) {
                    int kk = ks + tig + (u >> 1) * 4;
                    int rr = wm + 16 * i + grp + (u & 1) * 8;
                    float x = As[rr * 20 + kk];
                    float h = to_tf32(x);
                    ah[i][u] = U32(h);
                    if (TRIPLE) al[i][u] = U32(to_tf32(x - h));
                }
            #pragma unroll
            for (int j = 0; j < 4; ++j) {
                int cc = wn + 8 * j + grp;
                float x0 = B1[(ks + tig) * 72 + cc], x1 = B1[(ks + tig + 4) * 72 + cc];
                if (TRIPLE) {
                    float h0 = to_tf32(x0), h1 = to_tf32(x1);
                    uint32_t bh0 = U32(h0), bh1 = U32(h1);
                    uint32_t bl0 = U32(to_tf32(x0 - h0)), bl1 = U32(to_tf32(x1 - h1));
                    #pragma unroll
                    for (int i = 0; i < 2; ++i) {
                        MMA(c1[i][j], ah[i], bh0, bh1);
                        MMA(c1[i][j], ah[i], bl0, bl1);
                        MMA(c1[i][j], al[i], bh0, bh1);
                    }
                } else {
                    uint32_t bh0 = U32(to_tf32(x0)), bh1 = U32(to_tf32(x1));
                    #pragma unroll
                    for (int i = 0; i < 2; ++i) MMA(c1[i][j], ah[i], bh0, bh1);
                    if (DUAL) {
                        float y0 = B3[(ks + tig) * 72 + cc], y1 = B3[(ks + tig + 4) * 72 + cc];
                        uint32_t d0 = U32(to_tf32(y0)), d1 = U32(to_tf32(y1));
                        #pragma unroll
                        for (int i = 0; i < 2; ++i) MMA(c3[i][j], ah[i], d0, d1);
                    }
                }
            }
        }
        __syncthreads();
    }
}

// ---------------- RMSNorm ----------------
__global__ void rmsnorm_kernel(const float* __restrict__ x, const float* __restrict__ w,
                               float* __restrict__ out) {
    int t = blockIdx.x;
    const float* xr = x + (size_t)t * CD;
    float ss = 0.f;
    for (int d = threadIdx.x; d < CD; d += 256) { float v = xr[d]; ss += v * v; }
    __shared__ float red[256];
    red[threadIdx.x] = ss;
    __syncthreads();
    for (int s = 128; s > 0; s >>= 1) {
        if (threadIdx.x < s) red[threadIdx.x] += red[threadIdx.x + s];
        __syncthreads();
    }
    __shared__ float rinv;
    if (threadIdx.x == 0) rinv = rsqrtf(red[0] * (1.f / CD) + CEPS);
    __syncthreads();
    float* orow = out + (size_t)t * CD;
    for (int d = threadIdx.x; d < CD; d += 256) orow[d] = xr[d] * rinv * w[d];
}

// ---------------- fused QKV projection (3xTF32) ----------------
__global__ __launch_bounds__(256, 2) void qkv_kernel(
    const float* __restrict__ wq, const float* __restrict__ wk, const float* __restrict__ wv)
{
    __shared__ __align__(16) float smA[2 * ASTG];
    __shared__ __align__(16) float smB[2 * BSTG];
    int n0 = blockIdx.x * 64, m0 = blockIdx.y * 128, tid = threadIdx.x;
    const float* B; float* C; int ldb, nc;
    if (n0 < 1024)      { B = wq; C = g_q; ldb = 1024; nc = n0; }
    else if (n0 < 1280) { B = wk; C = g_k; ldb = 256;  nc = n0 - 1024; }
    else                { B = wv; C = g_v; ldb = 256;  nc = n0 - 1280; }
    const float* pA0 = g_xn + (size_t)(m0 + (tid >> 2)) * CD;
    const float* pA1 = pA0 + (size_t)64 * CD;
    const float* pB  = B + (size_t)(tid >> 4) * ldb + nc + (tid & 15) * 4;
    float c1[2][4][4] = {};
    mma_core<true, false>(pA0, pA1, pB, pB, ldb, CD, smA, smB, smB, tid, c1, c1);
    int lane = tid & 31, wid = tid >> 5, grp = lane >> 2, tig = lane & 3;
    int wm = (wid >> 1) * 32, wn = (wid & 1) * 32;
    #pragma unroll
    for (int i = 0; i < 2; ++i) {
        int r = m0 + wm + 16 * i + grp;
        #pragma unroll
        for (int j = 0; j < 4; ++j) {
            int cc = nc + wn + 8 * j + 2 * tig;
            *(float2*)&C[(size_t)r * ldb + cc]       = make_float2(c1[i][j][0], c1[i][j][1]);
            *(float2*)&C[(size_t)(r + 8) * ldb + cc] = make_float2(c1[i][j][2], c1[i][j][3]);
        }
    }
}

// ---------------- O projection + residual (3xTF32) ----------------
__global__ __launch_bounds__(256, 2) void oproj_kernel(
    const float* __restrict__ wo, const float* __restrict__ Res)
{
    __shared__ __align__(16) float smA[2 * ASTG];
    __shared__ __align__(16) float smB[2 * BSTG];
    int n0 = blockIdx.x * 64, m0 = blockIdx.y * 128, tid = threadIdx.x;
    const float* pA0 = g_att + (size_t)(m0 + (tid >> 2)) * CD;
    const float* pA1 = pA0 + (size_t)64 * CD;
    const float* pB  = wo + (size_t)(tid >> 4) * CD + n0 + (tid & 15) * 4;
    float c1[2][4][4] = {};
    mma_core<true, false>(pA0, pA1, pB, pB, CD, CD, smA, smB, smB, tid, c1, c1);
    int lane = tid & 31, wid = tid >> 5, grp = lane >> 2, tig = lane & 3;
    int wm = (wid >> 1) * 32, wn = (wid & 1) * 32;
    #pragma unroll
    for (int i = 0; i < 2; ++i) {
        int r = m0 + wm + 16 * i + grp;
        #pragma unroll
        for (int j = 0; j < 4; ++j) {
            int cc = n0 + wn + 8 * j + 2 * tig;
            size_t i0 = (size_t)r * CD + cc, i1 = (size_t)(r + 8) * CD + cc;
            float2 r0 = *(const float2*)&Res[i0], r1 = *(const float2*)&Res[i1];
            *(float2*)&g_h1[i0] = make_float2(c1[i][j][0] + r0.x, c1[i][j][1] + r0.y);
            *(float2*)&g_h1[i1] = make_float2(c1[i][j][2] + r1.x, c1[i][j][3] + r1.y);
        }
    }
}

// ---------------- RoPE ----------------
__global__ void rope_kernel(const int* __restrict__ pos_ids) {
    int idx = blockIdx.x * 256 + threadIdx.x;
    const int nq = CT * CH * 32, nk = CT * CKV * 32;
    if (idx >= nq + nk) return;
    float* base; int i, t;
    if (idx < nq) {
        i = idx & 31; int th = idx >> 5; int h = th % CH; t = th / CH;
        base = g_q + ((size_t)t * CH + h) * CHD;
    } else {
        int id2 = idx - nq;
        i = id2 & 31; int th = id2 >> 5; int h = th % CKV; t = th / CKV;
        base = g_k + ((size_t)t * CKV + h) * CHD;
    }
    float p = (float)pos_ids[t];
    float freq = expf(-(2.f * i / (float)CHD) * logf(10000.f));
    float ang = p * freq, c = cosf(ang), s = sinf(ang);
    float x0 = base[i], x1 = base[i + 32];
    base[i] = x0 * c - x1 * s;
    base[i + 32] = x1 * c + x0 * s;
}

// ---------------- flash attention v2: BM=128, 256 thr, pre-split K/V ----------------
// smem: Qs/P 128x72, Kh/Kl/Vh/Vl 64x72  => (128 + 4*64)*72*4 = 110592 B
constexpr int FL_SMEM = (128 * 72 + 4 * 64 * 72) * 4;
__global__ __launch_bounds__(256) void flash_mma() {
    extern __shared__ float fs[];
    float* Qs = fs;                      // Q staging, then P (raw fp32)
    float* Kh = fs + 128 * 72;
    float* Kl = Kh + 64 * 72;
    float* Vh = Kl + 64 * 72;
    float* Vl = Vh + 64 * 72;
    const uint32_t* KhU = (const uint32_t*)Kh;
    const uint32_t* KlU = (const uint32_t*)Kl;
    const uint32_t* VhU = (const uint32_t*)Vh;
    const uint32_t* VlU = (const uint32_t*)Vl;

    int bh = blockIdx.x, qt = 7 - blockIdx.y;     // heavy blocks first
    int b = bh >> 4, h = bh & 15, kvh = h >> 2;
    int tid = threadIdx.x, lane = tid & 31, warp = tid >> 5, grp = lane >> 2, tig = lane & 3;
    int rl0 = warp * 16 + grp;                    // local q row (0..127)

    // stage Q (scaled)
    #pragma unroll
    for (int it = 0; it < 8; ++it) {
        int idx = tid + it * 256;
        int r = idx >> 4, d4 = (idx & 15) * 4;
        float4 qv = *(const float4*)&g_q[((size_t)(b * CS + qt * 128 + r) * CH + h) * CHD + d4];
        Qs[r * 72 + d4]     = qv.x * 0.125f;
        Qs[r * 72 + d4 + 1] = qv.y * 0.125f;
        Qs[r * 72 + d4 + 2] = qv.z * 0.125f;
        Qs[r * 72 + d4 + 3] = qv.w * 0.125f;
    }
    __syncthreads();

    // Q fragments -> registers (hi/lo)
    uint32_t qh[8][4], ql[8][4];
    #pragma unroll
    for (int ks = 0; ks < 8; ++ks)
        #pragma unroll
        for (int u = 0; u < 4; ++u) {
            int kk = ks * 8 + tig + (u >> 1) * 4;
            int rr = warp * 16 + grp + (u & 1) * 8;
            float x = Qs[rr * 72 + kk];
            float hv = to_tf32(x);
            qh[ks][u] = U32(hv);
            ql[ks][u] = U32(to_tf32(x - hv));
        }

    float o[8][4] = {};
    float m0v = -INFINITY, m1v = -INFINITY, l0v = 0.f, l1v = 0.f;
    int ntiles = 2 * (qt + 1);

    for (int kt = 0; kt < ntiles; ++kt) {
        __syncthreads();   // frags extracted (iter0) / prior tile fully consumed
        // cooperative load + hi/lo split of K,V tile (64x64)
        #pragma unroll
        for (int it = 0; it < 4; ++it) {
            int idx = tid + it * 256;
            int n = idx >> 4, d4 = (idx & 15) * 4;
            size_t gb = ((size_t)(b * CS + kt * 64 + n) * CKV + kvh) * CHD + d4;
            float4 kv = *(const float4*)&g_k[gb];
            float4 vv = *(const float4*)&g_v[gb];
            const float* kp = (const float*)&kv;
            const float* vp = (const float*)&vv;
            #pragma unroll
            for (int jj = 0; jj < 4; ++jj) {
                float hk = to_tf32(kp[jj]);
                Kh[n * 72 + d4 + jj] = hk;
                Kl[n * 72 + d4 + jj] = to_tf32(kp[jj] - hk);
                float hv = to_tf32(vp[jj]);
                Vh[n * 72 + d4 + jj] = hv;
                Vl[n * 72 + d4 + jj] = to_tf32(vp[jj] - hv);
            }
        }
        __syncthreads();

        // S = Q K^T  (B frags are pure uint smem loads)
        float s[8][4] = {};
        #pragma unroll
        for (int ks = 0; ks < 8; ++ks)
            #pragma unroll
            for (int j = 0; j < 8; ++j) {
                int nrow = 8 * j + grp;
                uint32_t bh0 = KhU[nrow * 72 + ks * 8 + tig];
                uint32_t bh1 = KhU[nrow * 72 + ks * 8 + tig + 4];
                uint32_t bl0 = KlU[nrow * 72 + ks * 8 + tig];
                uint32_t bl1 = KlU[nrow * 72 + ks * 8 + tig + 4];
                MMA(s[j], qh[ks], bh0, bh1);
                MMA(s[j], qh[ks], bl0, bl1);
                MMA(s[j], ql[ks], bh0, bh1);
            }
        if (kt >= 2 * qt) {     // tiles that can cross the diagonal
            int rg0 = qt * 128 + rl0;
            #pragma unroll
            for (int j = 0; j < 8; ++j) {
                int cg = kt * 64 + 8 * j + 2 * tig;
                if (cg     > rg0)     s[j][0] = -INFINITY;
                if (cg + 1 > rg0)     s[j][1] = -INFINITY;
                if (cg     > rg0 + 8) s[j][2] = -INFINITY;
                if (cg + 1 > rg0 + 8) s[j][3] = -INFINITY;
            }
        }
        float mx0 = -INFINITY, mx1 = -INFINITY;
        #pragma unroll
        for (int j = 0; j < 8; ++j) {
            mx0 = fmaxf(mx0, fmaxf(s[j][0], s[j][1]));
            mx1 = fmaxf(mx1, fmaxf(s[j][2], s[j][3]));
        }
        mx0 = fmaxf(mx0, __shfl_xor_sync(0xffffffffu, mx0, 1));
        mx0 = fmaxf(mx0, __shfl_xor_sync(0xffffffffu, mx0, 2));
        mx1 = fmaxf(mx1, __shfl_xor_sync(0xffffffffu, mx1, 1));
        mx1 = fmaxf(mx1, __shfl_xor_sync(0xffffffffu, mx1, 2));
        float mn0 = fmaxf(m0v, mx0), mn1 = fmaxf(m1v, mx1);
        float al0 = expf(m0v - mn0), al1 = expf(m1v - mn1);
        float s0 = 0.f, s1 = 0.f;
        #pragma unroll
        for (int j = 0; j < 8; ++j) {
            s[j][0] = expf(s[j][0] - mn0); s[j][1] = expf(s[j][1] - mn0);
            s[j][2] = expf(s[j][2] - mn1); s[j][3] = expf(s[j][3] - mn1);
            s0 += s[j][0] + s[j][1];
            s1 += s[j][2] + s[j][3];
        }
        s0 += __shfl_xor_sync(0xffffffffu, s0, 1); s0 += __shfl_xor_sync(0xffffffffu, s0, 2);
        s1 += __shfl_xor_sync(0xffffffffu, s1, 1); s1 += __shfl_xor_sync(0xffffffffu, s1, 2);
        l0v = l0v * al0 + s0; l1v = l1v * al1 + s1;
        m0v = mn0; m1v = mn1;
        #pragma unroll
        for (int j = 0; j < 8; ++j) {
            o[j][0] *= al0; o[j][1] *= al0; o[j][2] *= al1; o[j][3] *= al1;
        }
        // P -> warp-private rows of Qs
        #pragma unroll
        for (int j = 0; j < 8; ++j) {
            int cc = 8 * j + 2 * tig;
            Qs[rl0 * 72 + cc]           = s[j][0];
            Qs[rl0 * 72 + cc + 1]       = s[j][1];
            Qs[(rl0 + 8) * 72 + cc]     = s[j][2];
            Qs[(rl0 + 8) * 72 + cc + 1] = s[j][3];
        }
        __syncwarp();
        // O += P V
        #pragma unroll
        for (int ks = 0; ks < 8; ++ks) {
            uint32_t ph[4], pl[4];
            #pragma unroll
            for (int u = 0; u < 4; ++u) {
                int kk = ks * 8 + tig + (u >> 1) * 4;
                int rr = warp * 16 + grp + (u & 1) * 8;
                float x = Qs[rr * 72 + kk];
                float hv = to_tf32(x);
                ph[u] = U32(hv);
                pl[u] = U32(to_tf32(x - hv));
            }
            #pragma unroll
            for (int j = 0; j < 8; ++j) {
                uint32_t vh0 = VhU[(ks * 8 + tig) * 72 + 8 * j + grp];
                uint32_t vh1 = VhU[(ks * 8 + tig + 4) * 72 + 8 * j + grp];
                uint32_t vl0 = VlU[(ks * 8 + tig) * 72 + 8 * j + grp];
                uint32_t vl1 = VlU[(ks * 8 + tig + 4) * 72 + 8 * j + grp];
                MMA(o[j], ph, vh0, vh1);
                MMA(o[j], ph, vl0, vl1);
                MMA(o[j], pl, vh0, vh1);
            }
        }
    }

    float i0 = 1.f / l0v, i1 = 1.f / l1v;
    size_t t0 = (size_t)(b * CS + qt * 128 + rl0);
    #pragma unroll
    for (int j = 0; j < 8; ++j) {
        int d = 8 * j + 2 * tig;
        *(float2*)&g_att[(t0 * CH + h) * CHD + d]       = make_float2(o[j][0] * i0, o[j][1] * i0);
        *(float2*)&g_att[((t0 + 8) * CH + h) * CHD + d] = make_float2(o[j][2] * i1, o[j][3] * i1);
    }
}

// ---------------- router ----------------
__global__ void router_kernel(const float* __restrict__ Gw, float* __restrict__ scores_out) {
    int gtid = blockIdx.x * blockDim.x + threadIdx.x;
    int warp = gtid >> 5, lane = threadIdx.x & 31;
    if (warp >= CT) return;
    const float* xr = g_hn + (size_t)warp * CD;
    float acc[CE] = {};
    for (int d = lane; d < CD; d += 32) {
        float xv = xr[d];
        const float* gr = Gw + (size_t)d * CE;
        #pragma unroll
        for (int e = 0; e < CE; ++e) acc[e] += xv * gr[e];
    }
    #pragma unroll
    for (int off = 16; off; off >>= 1)
        #pragma unroll
        for (int e = 0; e < CE; ++e) acc[e] += __shfl_down_sync(0xffffffffu, acc[e], off);
    if (lane == 0) {
        float mx = acc[0];
        #pragma unroll
        for (int e = 1; e < CE; ++e) mx = fmaxf(mx, acc[e]);
        float p[CE], sum = 0.f;
        #pragma unroll
        for (int e = 0; e < CE; ++e) { p[e] = expf(acc[e] - mx); sum += p[e]; }
        float inv = 1.f / sum;
        #pragma unroll
        for (int e = 0; e < CE; ++e) { p[e] *= inv; scores_out[(size_t)warp * CE + e] = p[e]; }
        int e0 = 0; float b0 = p[0];
        #pragma unroll
        for (int e = 1; e < CE; ++e) if (p[e] > b0) { b0 = p[e]; e0 = e; }
        int e1 = -1; float b1 = -1.f;
        #pragma unroll
        for (int e = 0; e < CE; ++e) if (e != e0 && p[e] > b1) { b1 = p[e]; e1 = e; }
        float wsum = b0 + b1;
        int p0 = atomicAdd(&g_cnt[e0], 1);
        g_tok[e0 * CT + p0] = warp; g_wsl[e0 * CT + p0] = b0 / wsum;
        g_slot[warp * 2 + 0] = e0 * CT + p0;
        int p1 = atomicAdd(&g_cnt[e1], 1);
        g_tok[e1 * CT + p1] = warp; g_wsl[e1 * CT + p1] = b1 / wsum;
        g_slot[warp * 2 + 1] = e1 * CT + p1;
    }
}

// ---------------- MoE up ----------------
__global__ __launch_bounds__(256, 2) void moe_up_mma(
    const float* __restrict__ W1, const float* __restrict__ W3)
{
    int e = blockIdx.z, cnt = g_cnt[e], r0 = blockIdx.y * 128;
    if (r0 >= cnt) return;
    int f0 = blockIdx.x * 64, tid = threadIdx.x;
    __shared__ __align__(16) float smA[2 * ASTG];
    __shared__ __align__(16) float smB1[2 * BSTG];
    __shared__ __align__(16) float smB3[2 * BSTG];
    __shared__ int toks[128]; __shared__ float wrow[128];
    if (tid < 128) {
        int rr = r0 + tid; bool ok = rr < cnt;
        toks[tid] = ok ? g_tok[e * CT + rr] : g_tok[e * CT];
        wrow[tid] = ok ? g_wsl[e * CT + rr] : 0.f;
    }
    __syncthreads();
    const float* pA0 = g_hn + (size_t)toks[tid >> 2] * CD;
    const float* pA1 = g_hn + (size_t)toks[(tid >> 2) + 64] * CD;
    const float* w1e = W1 + (size_t)e * CD * CF;
    const float* w3e = W3 + (size_t)e * CD * CF;
    const float* pB1 = w1e + (size_t)(tid >> 4) * CF + f0 + (tid & 15) * 4;
    const float* pB3 = w3e + (size_t)(tid >> 4) * CF + f0 + (tid & 15) * 4;
    float c1[2][4][4] = {}, c3[2][4][4] = {};
    mma_core<false, true>(pA0, pA1, pB1, pB3, CF, CD, smA, smB1, smB3, tid, c1, c3);
    int lane = tid & 31, wid = tid >> 5, grp = lane >> 2, tig = lane & 3;
    int wm = (wid >> 1) * 32, wn = (wid & 1) * 32;
    #pragma unroll
    for (int i = 0; i < 2; ++i) {
        int rloc = wm + 16 * i + grp;
        float w0 = wrow[rloc], w1v = wrow[rloc + 8];
        size_t rr0 = (size_t)e * CT + r0 + rloc;
        #pragma unroll
        for (int j = 0; j < 4; ++j) {
            int cc = f0 + wn + 8 * j + 2 * tig;
            float x0 = c1[i][j][0], x1 = c1[i][j][1], x2 = c1[i][j][2], x3 = c1[i][j][3];
            *(float2*)&g_hexp[rr0 * CF + cc] = make_float2(
                (x0 / (1.f + expf(-x0))) * c3[i][j][0] * w0,
                (x1 / (1.f + expf(-x1))) * c3[i][j][1] * w0);
            *(float2*)&g_hexp[(rr0 + 8) * CF + cc] = make_float2(
                (x2 / (1.f + expf(-x2))) * c3[i][j][2] * w1v,
                (x3 / (1.f + expf(-x3))) * c3[i][j][3] * w1v);
        }
    }
}

// ---------------- MoE down ----------------
__global__ __launch_bounds__(256, 2) void moe_down_mma(const float* __restrict__ W2) {
    int e = blockIdx.z, cnt = g_cnt[e], r0 = blockIdx.y * 128;
    if (r0 >= cnt) return;
    int n0 = blockIdx.x * 64, tid = threadIdx.x;
    __shared__ __align__(16) float smA[2 * ASTG];
    __shared__ __align__(16) float smB[2 * BSTG];
    const float* A = g_hexp + ((size_t)e * CT + r0) * CF;
    const float* B = W2 + (size_t)e * CF * CD;
    const float* pA0 = A + (size_t)(tid >> 2) * CF;
    const float* pA1 = pA0 + (size_t)64 * CF;
    const float* pB  = B + (size_t)(tid >> 4) * CD + n0 + (tid & 15) * 4;
    float c1[2][4][4] = {};
    mma_core<false, false>(pA0, pA1, pB, pB, CD, CF, smA, smB, smB, tid, c1, c1);
    float* C = g_y + ((size_t)e * CT + r0) * CD;
    int lane = tid & 31, wid = tid >> 5, grp = lane >> 2, tig = lane & 3;
    int wm = (wid >> 1) * 32, wn = (wid & 1) * 32;
    #pragma unroll
    for (int i = 0; i < 2; ++i) {
        int rloc = wm + 16 * i + grp;
        #pragma unroll
        for (int j = 0; j < 4; ++j) {
            int cc = n0 + wn + 8 * j + 2 * tig;
            *(float2*)&C[(size_t)rloc * CD + cc]       = make_float2(c1[i][j][0], c1[i][j][1]);
            *(float2*)&C[(size_t)(rloc + 8) * CD + cc] = make_float2(c1[i][j][2], c1[i][j][3]);
        }
    }
}

// ---------------- combine ----------------
__global__ void combine_kernel(float* __restrict__ out) {
    int idx = blockIdx.x * 256 + threadIdx.x;
    if (idx >= CT * CD) return;
    int t = idx >> 10, d = idx & 1023;
    int s0 = g_slot[t * 2 + 0], s1 = g_slot[t * 2 + 1];
    out[idx] = g_h1[idx] + g_y[(size_t)s0 * CD + d] + g_y[(size_t)s1 * CD + d];
}

// ---------------- launcher ----------------
extern "C" void kernel_launch(void* const* d_in, const int* in_sizes, int n_in,
                              void* d_out, int out_size) {
    const float* hid = (const float*)d_in[0];
    const int*   pos = (const int*)  d_in[1];
    const float* ln1 = (const float*)d_in[3];
    const float* ln2 = (const float*)d_in[4];
    const float* wq  = (const float*)d_in[5];
    const float* wk  = (const float*)d_in[6];
    const float* wv  = (const float*)d_in[7];
    const float* wo  = (const float*)d_in[8];
    const float* gw  = (const float*)d_in[9];
    const float* w1  = (const float*)d_in[10];
    const float* w3  = (const float*)d_in[11];
    const float* w2  = (const float*)d_in[12];
    float* out        = (float*)d_out;
    float* out_scores = out + (size_t)CT * CD;

    float* xn;  cudaGetSymbolAddress((void**)&xn,  g_xn);
    float* h1;  cudaGetSymbolAddress((void**)&h1,  g_h1);
    float* hn;  cudaGetSymbolAddress((void**)&hn,  g_hn);
    int*   cnt; cudaGetSymbolAddress((void**)&cnt, g_cnt);

    cudaFuncSetAttribute(flash_mma, cudaFuncAttributeMaxDynamicSharedMemorySize, FL_SMEM);

    rmsnorm_kernel<<<CT, 256>>>(hid, ln1, xn);
    qkv_kernel<<<dim3(24, 16), 256>>>(wq, wk, wv);
    {
        int total = CT * (CH + CKV) * 32;
        rope_kernel<<<(total + 255) / 256, 256>>>(pos);
    }
    flash_mma<<<dim3(CB * CH, CS / 128), 256, FL_SMEM>>>();
    oproj_kernel<<<dim3(16, 16), 256>>>(wo, hid);
    rmsnorm_kernel<<<CT, 256>>>(h1, ln2, hn);
    cudaMemsetAsync(cnt, 0, CE * sizeof(int));
    router_kernel<<<(CT * 32 + 255) / 256, 256>>>(gw, out_scores);
    moe_up_mma<<<dim3(CF / 64, CT / 128, CE), 256>>>(w1, w3);
    moe_down_mma<<<dim3(CD / 64, CT / 128, CE), 256>>>(w2);
    combine_kernel<<<(CT * CD + 255) / 256, 256>>>(out);
}